// round 6
// baseline (speedup 1.0000x reference)
#include <cuda_runtime.h>
#include <cstdint>

#define N_NODES 100000
#define N_EDGES 640000
#define HDIM 128
#define H2DIM 256
#define EDIM 16

// ---------------- scratch (device globals) ------------------------------------
__device__ float g_PQ [(size_t)N_NODES * 256];    // [node][0:128]=node@W1, [128:256]=node@W2
__device__ float g_MSG[(size_t)N_EDGES * HDIM];   // pre-BN messages
__device__ float g_Y  [(size_t)N_NODES * HDIM];   // scatter target
__device__ float g_H1 [(size_t)N_NODES * H2DIM];
__device__ float g_H2 [(size_t)N_NODES * H2DIM];
// BN stat slots: [0,128)=msg, [128,384)=bn1, [384,640)=bn2
__device__ float g_sum[640];
__device__ float g_sq [640];
__device__ float g_scaleArr[640];
__device__ float g_shiftArr[640];
__device__ int   g_cnt[8];

// packed tf32 weights
#define OFF_NODE 0        // [128][256]  W1 | W2
#define OFF_EDGE 32768    // [144][128]  W3 rows 0..127, We rows 128..143
#define OFF_M1   51200    // [128][256]
#define OFF_M2   83968    // [256][256]
#define OFF_M3   149504   // [256][128]
#define W_TOTAL  182272
__device__ unsigned g_Wbuf[W_TOTAL];

// ---------------- helpers ------------------------------------------------------
__device__ __forceinline__ unsigned f2tf32(float x) {
    unsigned r;
    asm("cvt.rna.tf32.f32 %0, %1;" : "=r"(r) : "f"(x));
    return r;
}

__device__ __forceinline__ void mma_tf32(float* c, const unsigned* a, const unsigned* b) {
    asm volatile(
        "mma.sync.aligned.m16n8k8.row.col.f32.tf32.tf32.f32 "
        "{%0,%1,%2,%3}, {%4,%5,%6,%7}, {%8,%9}, {%0,%1,%2,%3};"
        : "+f"(c[0]), "+f"(c[1]), "+f"(c[2]), "+f"(c[3])
        : "r"(a[0]), "r"(a[1]), "r"(a[2]), "r"(a[3]), "r"(b[0]), "r"(b[1]));
}

__device__ __forceinline__ void cp16(uint32_t dst, const void* src, bool pred) {
    int sz = pred ? 16 : 0;
    asm volatile("cp.async.cg.shared.global [%0], [%1], 16, %2;"
                 :: "r"(dst), "l"(src), "r"(sz));
}
__device__ __forceinline__ void cp_commit() { asm volatile("cp.async.commit_group;"); }
template <int N> __device__ __forceinline__ void cp_wait() {
    asm volatile("cp.async.wait_group %0;" :: "n"(N));
}
__device__ __forceinline__ uint32_t s2u(const void* p) {
    uint32_t a;
    asm("{ .reg .u64 t; cvta.to.shared.u64 t, %1; cvt.u32.u64 %0, t; }" : "=r"(a) : "l"(p));
    return a;
}
__device__ __forceinline__ void st_cs_v4(float* p, float4 v) {
    asm volatile("st.global.cs.v4.f32 [%0], {%1,%2,%3,%4};"
                 :: "l"(p), "f"(v.x), "f"(v.y), "f"(v.z), "f"(v.w) : "memory");
}
__device__ __forceinline__ float4 ld_cs_v4(const float* p) {
    float4 v;
    asm volatile("ld.global.cs.v4.f32 {%0,%1,%2,%3}, [%4];"
                 : "=f"(v.x), "=f"(v.y), "=f"(v.z), "=f"(v.w) : "l"(p));
    return v;
}

// GEMM smem geometry (128-row A tile, 3 stages)
#define G_AS_STAGE 18432             // 128*36*4
#define G_BS_STAGE 17408             // 32*136*4
#define G_AS_BYTES (3 * G_AS_STAGE)  // 55296
#define G_BS_BYTES (3 * G_BS_STAGE)  // 52224
#define G_PIPE (G_AS_BYTES + G_BS_BYTES)  // 107520
// edge smem geometry (64-row A tile, 2 stages)
#define E_AS_STAGE 9216              // 64*36*4
#define E_BS_STAGE 17408
#define E_AS_BYTES (2 * E_AS_STAGE)  // 18432
#define E_BS_BYTES (2 * E_BS_STAGE)  // 34816
#define E_PIPE (E_AS_BYTES + E_BS_BYTES)  // 53248

// ---------------- prep: weight convert + zero Y/stats/counters ------------------
__global__ void prep_zero_kernel(const float* __restrict__ W1, const float* __restrict__ W2,
                                 const float* __restrict__ W3, const float* __restrict__ We,
                                 const float* __restrict__ Wm1, const float* __restrict__ Wm2,
                                 const float* __restrict__ Wm3) {
    size_t i = (size_t)blockIdx.x * blockDim.x + threadIdx.x;
    if (i < 32768) {
        int k = (int)i >> 8, n = (int)i & 255;
        float v = (n < 128) ? W1[k * 128 + n] : W2[k * 128 + (n - 128)];
        g_Wbuf[OFF_NODE + i] = f2tf32(v);
    } else if (i < 51200) {
        int j = (int)i - 32768;
        float v = (j < 128 * 128) ? W3[j] : We[j - 128 * 128];
        g_Wbuf[OFF_EDGE + j] = f2tf32(v);
    } else if (i < 83968) {
        g_Wbuf[OFF_M1 + (i - 51200)] = f2tf32(Wm1[i - 51200]);
    } else if (i < 149504) {
        g_Wbuf[OFF_M2 + (i - 83968)] = f2tf32(Wm2[i - 83968]);
    } else if (i < W_TOTAL) {
        g_Wbuf[OFF_M3 + (i - 149504)] = f2tf32(Wm3[i - 149504]);
    }
    const size_t tot = (size_t)N_NODES * HDIM;
    const size_t stride = (size_t)gridDim.x * blockDim.x;
    for (size_t p = i; p < tot; p += stride) g_Y[p] = 0.f;
    if (i < 640) { g_sum[i] = 0.f; g_sq[i] = 0.f; }
    if (i < 8) g_cnt[i] = 0;
}

extern __shared__ char smem_raw[];

// ---------------- 3-stage pipelined tf32 GEMM, fused BN in + stats/finalize out --
// C[M,NC] = act(A) @ Wu (+cBias); act = relu(aScale[k]*x+aShift[k]) if aScale.
// If sSum: accumulate column stats; last CTA (counter) computes scale/shift.
__global__ void __launch_bounds__(256, 2) gemm_mma_kernel(
    const float* __restrict__ A, const unsigned* __restrict__ Wu,
    float* __restrict__ C, int M, int K, int NC,
    const float* __restrict__ aScale, const float* __restrict__ aShift,
    const float* __restrict__ cBias,
    float* __restrict__ sSum, float* __restrict__ sSq,
    const float* __restrict__ bnG, const float* __restrict__ bnB,
    float* __restrict__ scaleOut, float* __restrict__ shiftOut,
    float invCnt, int* cnt, int nCta, int finCols)
{
    float    (*As)[128][36]  = reinterpret_cast<float(*)[128][36]>(smem_raw);
    unsigned (*Bs)[32][136]  = reinterpret_cast<unsigned(*)[32][136]>(smem_raw + G_AS_BYTES);
    float    (*Cs)[132]      = reinterpret_cast<float(*)[132]>(smem_raw);   // overlay
    float* scs  = (float*)(smem_raw + G_PIPE);          // 256
    float* shs  = scs + 256;                            // 256
    float* red0 = shs + 256;                            // 128
    float* red1 = red0 + 128;                           // 128
    __shared__ int lastFlag;

    const int tid = threadIdx.x, lane = tid & 31, warp = tid >> 5;
    const int wm = (warp & 3) * 32, wn = (warp >> 2) * 64;
    const int bm = blockIdx.x * 128, bn = blockIdx.y * 128;
    const bool useBN = (aScale != nullptr);

    const uint32_t AsAddr = s2u(smem_raw);
    const uint32_t BsAddr = AsAddr + G_AS_BYTES;

    if (useBN && tid < K) { scs[tid] = aScale[tid]; shs[tid] = aShift[tid]; }

    auto issue_copy = [&](int t) {
        const int s = t % 3;
        const int k0 = t * 32;
#pragma unroll
        for (int l = 0; l < 4; l++) {
            int c = tid + l * 256;
            int row = c >> 3, cc = c & 7;
            int grow = bm + row;
            const float* src = A + (size_t)grow * K + k0 + cc * 4;
            uint32_t dst = AsAddr + (uint32_t)(s * G_AS_STAGE + (row * 36 + cc * 4) * 4);
            cp16(dst, src, grow < M);
        }
#pragma unroll
        for (int l = 0; l < 4; l++) {
            int c = tid + l * 256;
            int row = c >> 5, cc = c & 31;
            const unsigned* src = Wu + (size_t)(k0 + row) * NC + bn + cc * 4;
            uint32_t dst = BsAddr + (uint32_t)(s * G_BS_STAGE + (row * 136 + cc * 4) * 4);
            cp16(dst, src, true);
        }
        cp_commit();
    };

    float acc[2][8][4];
#pragma unroll
    for (int mt = 0; mt < 2; mt++)
#pragma unroll
        for (int nt = 0; nt < 8; nt++)
#pragma unroll
            for (int i = 0; i < 4; i++) acc[mt][nt][i] = 0.f;

    const int T = K >> 5;
    issue_copy(0);
    if (T > 1) issue_copy(1);

    for (int t = 0; t < T; t++) {
        if (t + 2 < T)      { issue_copy(t + 2); cp_wait<2>(); }
        else if (t + 1 < T) { cp_wait<1>(); }
        else                { cp_wait<0>(); }
        __syncthreads();
        const int s = t % 3;
        const int k0 = t * 32;
#pragma unroll
        for (int q = 0; q < 4; q++) {
            const int kr = q * 8 + (lane & 3);
            float s0 = 1.f, h0 = 0.f, s4 = 1.f, h4 = 0.f;
            if (useBN) {
                s0 = scs[k0 + kr];     h0 = shs[k0 + kr];
                s4 = scs[k0 + kr + 4]; h4 = shs[k0 + kr + 4];
            }
            unsigned af[2][4], bf[8][2];
#pragma unroll
            for (int mt = 0; mt < 2; mt++) {
                int m = wm + mt * 16 + (lane >> 2);
                float a0 = As[s][m][kr],     a1 = As[s][m + 8][kr];
                float a2 = As[s][m][kr + 4], a3 = As[s][m + 8][kr + 4];
                if (useBN) {
                    a0 = fmaxf(fmaf(a0, s0, h0), 0.f);
                    a1 = fmaxf(fmaf(a1, s0, h0), 0.f);
                    a2 = fmaxf(fmaf(a2, s4, h4), 0.f);
                    a3 = fmaxf(fmaf(a3, s4, h4), 0.f);
                }
                af[mt][0] = f2tf32(a0); af[mt][1] = f2tf32(a1);
                af[mt][2] = f2tf32(a2); af[mt][3] = f2tf32(a3);
            }
#pragma unroll
            for (int nt = 0; nt < 8; nt++) {
                int n = wn + nt * 8 + (lane >> 2);
                bf[nt][0] = Bs[s][kr][n];
                bf[nt][1] = Bs[s][kr + 4][n];
            }
#pragma unroll
            for (int mt = 0; mt < 2; mt++)
#pragma unroll
                for (int nt = 0; nt < 8; nt++)
                    mma_tf32(acc[mt][nt], af[mt], bf[nt]);
        }
        __syncthreads();
    }

    // ---------------- epilogue: stage -> smem, warp-per-row coalesced ----------
#pragma unroll
    for (int mt = 0; mt < 2; mt++)
#pragma unroll
        for (int half = 0; half < 2; half++) {
            int r = wm + mt * 16 + (lane >> 2) + half * 8;
#pragma unroll
            for (int nt = 0; nt < 8; nt++) {
                int cl = wn + nt * 8 + 2 * (lane & 3);
                float2 v; v.x = acc[mt][nt][half * 2 + 0]; v.y = acc[mt][nt][half * 2 + 1];
                *(float2*)&Cs[r][cl] = v;
            }
        }
    if (sSum && tid < 128) { red0[tid] = 0.f; red1[tid] = 0.f; }
    __syncthreads();

    float4 bias = make_float4(0.f, 0.f, 0.f, 0.f);
    if (cBias) bias = *(const float4*)(cBias + bn + lane * 4);
    float psum[4] = {0.f, 0.f, 0.f, 0.f}, psq[4] = {0.f, 0.f, 0.f, 0.f};

#pragma unroll
    for (int i = 0; i < 16; i++) {
        int r = warp * 16 + i;
        int R = bm + r;
        if (R < M) {
            float4 v = *(const float4*)&Cs[r][lane * 4];
            v.x += bias.x; v.y += bias.y; v.z += bias.z; v.w += bias.w;
            *(float4*)(C + (size_t)R * NC + bn + lane * 4) = v;
            psum[0] += v.x; psum[1] += v.y; psum[2] += v.z; psum[3] += v.w;
            psq[0] += v.x * v.x; psq[1] += v.y * v.y;
            psq[2] += v.z * v.z; psq[3] += v.w * v.w;
        }
    }

    if (sSum) {
        __syncthreads();
#pragma unroll
        for (int j = 0; j < 4; j++) {
            atomicAdd(&red0[lane * 4 + j], psum[j]);
            atomicAdd(&red1[lane * 4 + j], psq[j]);
        }
        __syncthreads();
        if (tid < 128) {
            atomicAdd(&sSum[bn + tid], red0[tid]);
            atomicAdd(&sSq [bn + tid], red1[tid]);
        }
        // grid-completion fused BN finalize
        __threadfence();
        if (tid == 0) lastFlag = (atomicAdd(cnt, 1) == nCta - 1) ? 1 : 0;
        __syncthreads();
        if (lastFlag) {
            for (int c = tid; c < finCols; c += 256) {
                float mean = sSum[c] * invCnt;
                float var  = fmaxf(sSq[c] * invCnt - mean * mean, 0.f);
                float a = bnG[c] * rsqrtf(var + 1e-5f);
                scaleOut[c] = a;
                shiftOut[c] = fmaf(-mean, a, bnB[c]);
            }
            if (tid == 0) *cnt = 0;
        }
    }
}

// ---------------- pipelined edge message kernel (64-row, fused finalize) --------
// MSG[e] = edge_rep[e]@W3 + edge_attr[e]@We + be + P[src[e]] + Q[dst[e]], + stats
__global__ void __launch_bounds__(256, 3) edge_msg_kernel(
    const float* __restrict__ edge_rep, const float* __restrict__ edge_attr,
    const int* __restrict__ src, const int* __restrict__ dst,
    const float* __restrict__ be,
    const float* __restrict__ bng, const float* __restrict__ bnb)
{
    float    (*As)[64][36]  = reinterpret_cast<float(*)[64][36]>(smem_raw);
    unsigned (*Bs)[32][136] = reinterpret_cast<unsigned(*)[32][136]>(smem_raw + E_AS_BYTES);
    float    (*Cs)[132]     = reinterpret_cast<float(*)[132]>(smem_raw);   // overlay
    float* red0 = (float*)(smem_raw + E_PIPE);
    float* red1 = red0 + 128;
    __shared__ int lastFlag;

    const int tid = threadIdx.x, lane = tid & 31, warp = tid >> 5;
    const int wm = (warp & 1) * 32, wn = (warp >> 1) * 32;
    const size_t bm = (size_t)blockIdx.x * 64;

    const uint32_t AsAddr = s2u(smem_raw);
    const uint32_t BsAddr = AsAddr + E_AS_BYTES;
    const unsigned* Wu = g_Wbuf + OFF_EDGE;

    // L2 prefetch of the P/Q gather rows (hidden behind mainloop)
    if (tid < 128) {
        int e0 = (int)bm + (tid >> 1);
        const float* row = (tid & 1) ? (g_PQ + (size_t)dst[e0] * 256 + 128)
                                     : (g_PQ + (size_t)src[e0] * 256);
#pragma unroll
        for (int j = 0; j < 4; j++)
            asm volatile("prefetch.global.L2 [%0];" :: "l"(row + j * 32));
    }

    auto issue_copy = [&](int t) {
        const int s = t & 1;
        if (t < 4) {
            const int k0 = t * 32;
#pragma unroll
            for (int l = 0; l < 2; l++) {
                int c = tid + l * 256;
                int row = c >> 3, cc = c & 7;
                const float* sp = edge_rep + (bm + row) * HDIM + k0 + cc * 4;
                uint32_t dp = AsAddr + (uint32_t)(s * E_AS_STAGE + (row * 36 + cc * 4) * 4);
                cp16(dp, sp, true);
            }
#pragma unroll
            for (int l = 0; l < 4; l++) {
                int c = tid + l * 256;
                int row = c >> 5, cc = c & 31;
                const unsigned* sp = Wu + (size_t)(k0 + row) * HDIM + cc * 4;
                uint32_t dp = BsAddr + (uint32_t)(s * E_BS_STAGE + (row * 136 + cc * 4) * 4);
                cp16(dp, sp, true);
            }
        } else {
            // edge encoder tail: K=16
            {
                int row = tid >> 2, cc = tid & 3;
                const float* sp = edge_attr + (bm + row) * EDIM + cc * 4;
                uint32_t dp = AsAddr + (uint32_t)(s * E_AS_STAGE + (row * 36 + cc * 4) * 4);
                cp16(dp, sp, true);
            }
#pragma unroll
            for (int l = 0; l < 2; l++) {
                int c = tid + l * 256;
                int row = c >> 5, cc = c & 31;
                const unsigned* sp = Wu + (size_t)(128 + row) * HDIM + cc * 4;
                uint32_t dp = BsAddr + (uint32_t)(s * E_BS_STAGE + (row * 136 + cc * 4) * 4);
                cp16(dp, sp, true);
            }
        }
        cp_commit();
    };

    float acc[2][4][4];
#pragma unroll
    for (int mt = 0; mt < 2; mt++)
#pragma unroll
        for (int nt = 0; nt < 4; nt++)
#pragma unroll
            for (int i = 0; i < 4; i++) acc[mt][nt][i] = 0.f;

    issue_copy(0);

    for (int t = 0; t < 5; t++) {
        cp_wait<0>();
        __syncthreads();
        if (t + 1 < 5) issue_copy(t + 1);
        const int s = t & 1;
        const int qmax = (t < 4) ? 4 : 2;
        for (int q = 0; q < qmax; q++) {
            const int kr = q * 8 + (lane & 3);
            unsigned af[2][4], bf[4][2];
#pragma unroll
            for (int mt = 0; mt < 2; mt++) {
                int m = wm + mt * 16 + (lane >> 2);
                af[mt][0] = f2tf32(As[s][m][kr]);
                af[mt][1] = f2tf32(As[s][m + 8][kr]);
                af[mt][2] = f2tf32(As[s][m][kr + 4]);
                af[mt][3] = f2tf32(As[s][m + 8][kr + 4]);
            }
#pragma unroll
            for (int nt = 0; nt < 4; nt++) {
                int n = wn + nt * 8 + (lane >> 2);
                bf[nt][0] = Bs[s][kr][n];
                bf[nt][1] = Bs[s][kr + 4][n];
            }
#pragma unroll
            for (int mt = 0; mt < 2; mt++)
#pragma unroll
                for (int nt = 0; nt < 4; nt++)
                    mma_tf32(acc[mt][nt], af[mt], bf[nt]);
        }
        __syncthreads();
    }

    // ---------------- epilogue: stage -> smem, warp-per-edge coalesced ---------
#pragma unroll
    for (int mt = 0; mt < 2; mt++)
#pragma unroll
        for (int half = 0; half < 2; half++) {
            int r = wm + mt * 16 + (lane >> 2) + half * 8;
#pragma unroll
            for (int nt = 0; nt < 4; nt++) {
                int cl = wn + nt * 8 + 2 * (lane & 3);
                float2 v; v.x = acc[mt][nt][half * 2 + 0]; v.y = acc[mt][nt][half * 2 + 1];
                *(float2*)&Cs[r][cl] = v;
            }
        }
    if (tid < 128) { red0[tid] = 0.f; red1[tid] = 0.f; }
    __syncthreads();

    float4 bev = *(const float4*)(be + lane * 4);
    float psum[4] = {0.f, 0.f, 0.f, 0.f}, psq[4] = {0.f, 0.f, 0.f, 0.f};

#pragma unroll
    for (int i = 0; i < 8; i++) {
        int r = warp * 8 + i;
        size_t e = bm + r;
        int s = src[e], d = dst[e];
        float4 pv = *(const float4*)(g_PQ + (size_t)s * 256 + lane * 4);
        float4 qv = *(const float4*)(g_PQ + (size_t)d * 256 + 128 + lane * 4);
        float4 v = *(const float4*)&Cs[r][lane * 4];
        v.x += pv.x + qv.x + bev.x;
        v.y += pv.y + qv.y + bev.y;
        v.z += pv.z + qv.z + bev.z;
        v.w += pv.w + qv.w + bev.w;
        st_cs_v4(g_MSG + e * HDIM + lane * 4, v);   // streaming: keep PQ in L2
        psum[0] += v.x; psum[1] += v.y; psum[2] += v.z; psum[3] += v.w;
        psq[0] += v.x * v.x; psq[1] += v.y * v.y;
        psq[2] += v.z * v.z; psq[3] += v.w * v.w;
    }

    __syncthreads();
#pragma unroll
    for (int j = 0; j < 4; j++) {
        atomicAdd(&red0[lane * 4 + j], psum[j]);
        atomicAdd(&red1[lane * 4 + j], psq[j]);
    }
    __syncthreads();
    if (tid < 128) {
        atomicAdd(&g_sum[tid], red0[tid]);
        atomicAdd(&g_sq [tid], red1[tid]);
    }

    // grid-completion fused BN finalize (msg BN, slot 0)
    __threadfence();
    if (tid == 0) lastFlag = (atomicAdd(&g_cnt[0], 1) == (N_EDGES / 64) - 1) ? 1 : 0;
    __syncthreads();
    if (lastFlag) {
        if (tid < 128) {
            float mean = g_sum[tid] * (1.f / (float)N_EDGES);
            float var  = fmaxf(g_sq[tid] * (1.f / (float)N_EDGES) - mean * mean, 0.f);
            float a = bng[tid] * rsqrtf(var + 1e-5f);
            g_scaleArr[tid] = a;
            g_shiftArr[tid] = fmaf(-mean, a, bnb[tid]);
        }
        if (tid == 0) g_cnt[0] = 0;
    }
}

// ---------------- BN+ReLU+scatter with vector red ------------------------------
__global__ void scatter_kernel(const int* __restrict__ dst) {
    unsigned t = blockIdx.x * blockDim.x + threadIdx.x;
    size_t e = (size_t)(t >> 5);
    int c4 = (t & 31) * 4;
    if (e < (size_t)N_EDGES) {
        int d = dst[e];
        float4 m = ld_cs_v4(g_MSG + e * HDIM + c4);
        float v0 = fmaxf(fmaf(m.x, g_scaleArr[c4 + 0], g_shiftArr[c4 + 0]), 0.f);
        float v1 = fmaxf(fmaf(m.y, g_scaleArr[c4 + 1], g_shiftArr[c4 + 1]), 0.f);
        float v2 = fmaxf(fmaf(m.z, g_scaleArr[c4 + 2], g_shiftArr[c4 + 2]), 0.f);
        float v3 = fmaxf(fmaf(m.w, g_scaleArr[c4 + 3], g_shiftArr[c4 + 3]), 0.f);
        float* p = g_Y + (size_t)d * HDIM + c4;
        asm volatile("red.global.add.v4.f32 [%0], {%1,%2,%3,%4};"
                     :: "l"(p), "f"(v0), "f"(v1), "f"(v2), "f"(v3) : "memory");
    }
}

// ---------------- launch ------------------------------------------------------
extern "C" void kernel_launch(void* const* d_in, const int* in_sizes, int n_in,
                              void* d_out, int out_size) {
    const float* node_rep  = (const float*)d_in[0];
    const float* edge_rep  = (const float*)d_in[1];
    const float* edge_attr = (const float*)d_in[2];
    const int*   eidx      = (const int*)d_in[3];
    const float* W1  = (const float*)d_in[4];
    const float* W2  = (const float*)d_in[5];
    const float* W3  = (const float*)d_in[6];
    const float* We  = (const float*)d_in[7];
    const float* be  = (const float*)d_in[8];
    const float* bng = (const float*)d_in[9];
    const float* bnb = (const float*)d_in[10];
    const float* Wm1 = (const float*)d_in[11];
    const float* g1  = (const float*)d_in[12];
    const float* b1  = (const float*)d_in[13];
    const float* Wm2 = (const float*)d_in[14];
    const float* g2  = (const float*)d_in[15];
    const float* b2  = (const float*)d_in[16];
    const float* Wm3 = (const float*)d_in[17];
    const float* bm3 = (const float*)d_in[18];
    float* out = (float*)d_out;

    const int* src = eidx;
    const int* dst = eidx + N_EDGES;

    float *PQ, *Y, *H1, *H2, *SUM, *SQ, *SCALE, *SHIFT;
    unsigned* WB; int* CNT;
    cudaGetSymbolAddress((void**)&PQ, g_PQ);
    cudaGetSymbolAddress((void**)&Y,  g_Y);
    cudaGetSymbolAddress((void**)&H1, g_H1);
    cudaGetSymbolAddress((void**)&H2, g_H2);
    cudaGetSymbolAddress((void**)&SUM,   g_sum);
    cudaGetSymbolAddress((void**)&SQ,    g_sq);
    cudaGetSymbolAddress((void**)&SCALE, g_scaleArr);
    cudaGetSymbolAddress((void**)&SHIFT, g_shiftArr);
    cudaGetSymbolAddress((void**)&WB, g_Wbuf);
    cudaGetSymbolAddress((void**)&CNT, g_cnt);

    const int GEMM_SMEM = G_PIPE + 2048 + 1024;   // 110592
    const int EDGE_SMEM = E_PIPE + 1024;          // 54272
    cudaFuncSetAttribute(gemm_mma_kernel, cudaFuncAttributeMaxDynamicSharedMemorySize, GEMM_SMEM);
    cudaFuncSetAttribute(edge_msg_kernel, cudaFuncAttributeMaxDynamicSharedMemorySize, EDGE_SMEM);

    const int MBLK = (N_NODES + 127) / 128;  // 782

    prep_zero_kernel<<<4096, 256>>>(W1, W2, W3, We, Wm1, Wm2, Wm3);

    // fused node linears: PQ = node_rep @ [W1|W2]
    gemm_mma_kernel<<<dim3(MBLK, 2), 256, GEMM_SMEM>>>(
        node_rep, WB + OFF_NODE, PQ, N_NODES, HDIM, 256,
        nullptr, nullptr, nullptr, nullptr, nullptr,
        nullptr, nullptr, nullptr, nullptr, 0.f, nullptr, 0, 0);

    // edge GEMM + encoder + gathers + BN stats + fused msg BN finalize
    edge_msg_kernel<<<N_EDGES / 64, 256, EDGE_SMEM>>>(
        edge_rep, edge_attr, src, dst, be, bng, bnb);

    // BN + ReLU + scatter-sum
    scatter_kernel<<<(N_EDGES * 32) / 256, 256>>>(dst);

    // MLP layer 1 (+ fused bn1 finalize)
    gemm_mma_kernel<<<dim3(MBLK, 2), 256, GEMM_SMEM>>>(
        Y, WB + OFF_M1, H1, N_NODES, HDIM, H2DIM,
        nullptr, nullptr, nullptr, SUM + 128, SQ + 128,
        g1, b1, SCALE + 128, SHIFT + 128,
        1.f / (float)N_NODES, CNT + 1, MBLK * 2, 256);

    // MLP layer 2 (+ fused bn2 finalize)
    gemm_mma_kernel<<<dim3(MBLK, 2), 256, GEMM_SMEM>>>(
        H1, WB + OFF_M2, H2, N_NODES, H2DIM, H2DIM,
        SCALE + 128, SHIFT + 128, nullptr, SUM + 384, SQ + 384,
        g2, b2, SCALE + 384, SHIFT + 384,
        1.f / (float)N_NODES, CNT + 2, MBLK * 2, 256);

    // MLP layer 3
    gemm_mma_kernel<<<dim3(MBLK, 1), 256, GEMM_SMEM>>>(
        H2, WB + OFF_M3, out, N_NODES, H2DIM, HDIM,
        SCALE + 384, SHIFT + 384, bm3, nullptr, nullptr,
        nullptr, nullptr, nullptr, nullptr, 0.f, nullptr, 0, 0);
}

// round 7
// speedup vs baseline: 1.0778x; 1.0778x over previous
#include <cuda_runtime.h>
#include <cstdint>

#define N_NODES 100000
#define N_EDGES 640000
#define HDIM 128
#define H2DIM 256
#define EDIM 16

// ---------------- scratch (device globals) ------------------------------------
__device__ float g_PQ [(size_t)N_NODES * 256];    // [node][0:128]=node@W1, [128:256]=node@W2
__device__ float g_MSG[(size_t)N_EDGES * HDIM];   // pre-BN messages
__device__ float g_Y  [(size_t)N_NODES * HDIM];   // scatter target
__device__ float g_H1 [(size_t)N_NODES * H2DIM];
__device__ float g_H2 [(size_t)N_NODES * H2DIM];
// BN stat slots: [0,128)=msg, [128,384)=bn1, [384,640)=bn2
__device__ float g_sum[640];
__device__ float g_sq [640];
__device__ float g_scaleArr[640];
__device__ float g_shiftArr[640];

// packed tf32 weights
#define OFF_NODE 0        // [128][256]  W1 | W2
#define OFF_EDGE 32768    // [144][128]  W3 rows 0..127, We rows 128..143
#define OFF_M1   51200    // [128][256]
#define OFF_M2   83968    // [256][256]
#define OFF_M3   149504   // [256][128]
#define W_TOTAL  182272
__device__ unsigned g_Wbuf[W_TOTAL];

// ---------------- helpers ------------------------------------------------------
__device__ __forceinline__ unsigned f2tf32(float x) {
    unsigned r;
    asm("cvt.rna.tf32.f32 %0, %1;" : "=r"(r) : "f"(x));
    return r;
}

__device__ __forceinline__ void mma_tf32(float* c, const unsigned* a, const unsigned* b) {
    asm volatile(
        "mma.sync.aligned.m16n8k8.row.col.f32.tf32.tf32.f32 "
        "{%0,%1,%2,%3}, {%4,%5,%6,%7}, {%8,%9}, {%0,%1,%2,%3};"
        : "+f"(c[0]), "+f"(c[1]), "+f"(c[2]), "+f"(c[3])
        : "r"(a[0]), "r"(a[1]), "r"(a[2]), "r"(a[3]), "r"(b[0]), "r"(b[1]));
}

__device__ __forceinline__ void cp16(uint32_t dst, const void* src, bool pred) {
    int sz = pred ? 16 : 0;
    asm volatile("cp.async.cg.shared.global [%0], [%1], 16, %2;"
                 :: "r"(dst), "l"(src), "r"(sz));
}
__device__ __forceinline__ void cp_commit() { asm volatile("cp.async.commit_group;"); }
template <int N> __device__ __forceinline__ void cp_wait() {
    asm volatile("cp.async.wait_group %0;" :: "n"(N));
}
__device__ __forceinline__ uint32_t s2u(const void* p) {
    uint32_t a;
    asm("{ .reg .u64 t; cvta.to.shared.u64 t, %1; cvt.u32.u64 %0, t; }" : "=r"(a) : "l"(p));
    return a;
}

// GEMM smem geometry (128-row A tile, 3 stages)
#define G_AS_STAGE 18432             // 128*36*4
#define G_BS_STAGE 17408             // 32*136*4
#define G_AS_BYTES (3 * G_AS_STAGE)  // 55296
#define G_BS_BYTES (3 * G_BS_STAGE)  // 52224
#define G_PIPE (G_AS_BYTES + G_BS_BYTES)  // 107520
// edge smem geometry (64-row A tile, 2 stages)
#define E_AS_STAGE 9216              // 64*36*4
#define E_BS_STAGE 17408
#define E_AS_BYTES (2 * E_AS_STAGE)  // 18432
#define E_BS_BYTES (2 * E_BS_STAGE)  // 34816
#define E_PIPE (E_AS_BYTES + E_BS_BYTES)  // 53248

// ---------------- utility kernels ----------------------------------------------
__global__ void prep_kernel(const float* __restrict__ W1, const float* __restrict__ W2,
                            const float* __restrict__ W3, const float* __restrict__ We,
                            const float* __restrict__ Wm1, const float* __restrict__ Wm2,
                            const float* __restrict__ Wm3) {
    int i = blockIdx.x * blockDim.x + threadIdx.x;
    if (i < 32768) {
        int k = i >> 8, n = i & 255;
        float v = (n < 128) ? W1[k * 128 + n] : W2[k * 128 + (n - 128)];
        g_Wbuf[OFF_NODE + i] = f2tf32(v);
    } else if (i < 51200) {
        int j = i - 32768;
        float v = (j < 128 * 128) ? W3[j] : We[j - 128 * 128];
        g_Wbuf[OFF_EDGE + j] = f2tf32(v);
    } else if (i < 83968) {
        g_Wbuf[OFF_M1 + (i - 51200)] = f2tf32(Wm1[i - 51200]);
    } else if (i < 149504) {
        g_Wbuf[OFF_M2 + (i - 83968)] = f2tf32(Wm2[i - 83968]);
    } else if (i < W_TOTAL) {
        g_Wbuf[OFF_M3 + (i - 149504)] = f2tf32(Wm3[i - 149504]);
    }
}

__global__ void zero_y_stats_kernel() {
    size_t i = (size_t)blockIdx.x * blockDim.x + threadIdx.x;
    const size_t tot = (size_t)N_NODES * HDIM;
    const size_t stride = (size_t)gridDim.x * blockDim.x;
    for (size_t p = i; p < tot; p += stride) g_Y[p] = 0.f;
    if (i < 640) { g_sum[i] = 0.f; g_sq[i] = 0.f; }
}

__global__ void bn_finalize_kernel(const float* __restrict__ g,
                                   const float* __restrict__ b,
                                   int off, int cols, float invCnt) {
    int c = blockIdx.x * blockDim.x + threadIdx.x;
    if (c < cols) {
        float mean = g_sum[off + c] * invCnt;
        float var  = fmaxf(g_sq[off + c] * invCnt - mean * mean, 0.f);
        float a = g[c] * rsqrtf(var + 1e-5f);
        g_scaleArr[off + c] = a;
        g_shiftArr[off + c] = fmaf(-mean, a, b[c]);
    }
}

extern __shared__ char smem_raw[];

// ---------------- 3-stage pipelined tf32 GEMM with fused BN ---------------------
// C[M,NC] = act(A) @ Wu (+cBias); act = relu(aScale[k]*x+aShift[k]) if aScale.
// Grid: (NC/128, ceil(M/128)) — column blocks adjacent in launch order so the
// second read of an A row-block hits L2.
__global__ void __launch_bounds__(256, 2) gemm_mma_kernel(
    const float* __restrict__ A, const unsigned* __restrict__ Wu,
    float* __restrict__ C, int M, int K, int NC,
    const float* __restrict__ aScale, const float* __restrict__ aShift,
    const float* __restrict__ cBias,
    float* __restrict__ sSum, float* __restrict__ sSq)
{
    float    (*As)[128][36]  = reinterpret_cast<float(*)[128][36]>(smem_raw);
    unsigned (*Bs)[32][136]  = reinterpret_cast<unsigned(*)[32][136]>(smem_raw + G_AS_BYTES);
    float    (*Cs)[132]      = reinterpret_cast<float(*)[132]>(smem_raw);   // overlay
    float* scs  = (float*)(smem_raw + G_PIPE);          // 256
    float* shs  = scs + 256;                            // 256
    float* red0 = shs + 256;                            // 128
    float* red1 = red0 + 128;                           // 128

    const int tid = threadIdx.x, lane = tid & 31, warp = tid >> 5;
    const int wm = (warp & 3) * 32, wn = (warp >> 2) * 64;
    const int bm = blockIdx.y * 128, bn = blockIdx.x * 128;
    const bool useBN = (aScale != nullptr);

    const uint32_t AsAddr = s2u(smem_raw);
    const uint32_t BsAddr = AsAddr + G_AS_BYTES;

    if (useBN && tid < K) { scs[tid] = aScale[tid]; shs[tid] = aShift[tid]; }

    auto issue_copy = [&](int t) {
        const int s = t % 3;
        const int k0 = t * 32;
#pragma unroll
        for (int l = 0; l < 4; l++) {
            int c = tid + l * 256;
            int row = c >> 3, cc = c & 7;
            int grow = bm + row;
            const float* src = A + (size_t)grow * K + k0 + cc * 4;
            uint32_t dst = AsAddr + (uint32_t)(s * G_AS_STAGE + (row * 36 + cc * 4) * 4);
            cp16(dst, src, grow < M);
        }
#pragma unroll
        for (int l = 0; l < 4; l++) {
            int c = tid + l * 256;
            int row = c >> 5, cc = c & 31;
            const unsigned* src = Wu + (size_t)(k0 + row) * NC + bn + cc * 4;
            uint32_t dst = BsAddr + (uint32_t)(s * G_BS_STAGE + (row * 136 + cc * 4) * 4);
            cp16(dst, src, true);
        }
        cp_commit();
    };

    float acc[2][8][4];
#pragma unroll
    for (int mt = 0; mt < 2; mt++)
#pragma unroll
        for (int nt = 0; nt < 8; nt++)
#pragma unroll
            for (int i = 0; i < 4; i++) acc[mt][nt][i] = 0.f;

    const int T = K >> 5;
    issue_copy(0);
    if (T > 1) issue_copy(1);

    for (int t = 0; t < T; t++) {
        if (t + 2 < T)      { issue_copy(t + 2); cp_wait<2>(); }
        else if (t + 1 < T) { cp_wait<1>(); }
        else                { cp_wait<0>(); }
        __syncthreads();
        const int s = t % 3;
        const int k0 = t * 32;
#pragma unroll
        for (int q = 0; q < 4; q++) {
            const int kr = q * 8 + (lane & 3);
            float s0 = 1.f, h0 = 0.f, s4 = 1.f, h4 = 0.f;
            if (useBN) {
                s0 = scs[k0 + kr];     h0 = shs[k0 + kr];
                s4 = scs[k0 + kr + 4]; h4 = shs[k0 + kr + 4];
            }
            unsigned af[2][4], bf[8][2];
#pragma unroll
            for (int mt = 0; mt < 2; mt++) {
                int m = wm + mt * 16 + (lane >> 2);
                float a0 = As[s][m][kr],     a1 = As[s][m + 8][kr];
                float a2 = As[s][m][kr + 4], a3 = As[s][m + 8][kr + 4];
                if (useBN) {
                    a0 = fmaxf(fmaf(a0, s0, h0), 0.f);
                    a1 = fmaxf(fmaf(a1, s0, h0), 0.f);
                    a2 = fmaxf(fmaf(a2, s4, h4), 0.f);
                    a3 = fmaxf(fmaf(a3, s4, h4), 0.f);
                }
                af[mt][0] = f2tf32(a0); af[mt][1] = f2tf32(a1);
                af[mt][2] = f2tf32(a2); af[mt][3] = f2tf32(a3);
            }
#pragma unroll
            for (int nt = 0; nt < 8; nt++) {
                int n = wn + nt * 8 + (lane >> 2);
                bf[nt][0] = Bs[s][kr][n];
                bf[nt][1] = Bs[s][kr + 4][n];
            }
#pragma unroll
            for (int mt = 0; mt < 2; mt++)
#pragma unroll
                for (int nt = 0; nt < 8; nt++)
                    mma_tf32(acc[mt][nt], af[mt], bf[nt]);
        }
        __syncthreads();
    }

    // ---------------- epilogue: stage -> smem, warp-per-row coalesced ----------
#pragma unroll
    for (int mt = 0; mt < 2; mt++)
#pragma unroll
        for (int half = 0; half < 2; half++) {
            int r = wm + mt * 16 + (lane >> 2) + half * 8;
#pragma unroll
            for (int nt = 0; nt < 8; nt++) {
                int cl = wn + nt * 8 + 2 * (lane & 3);
                float2 v; v.x = acc[mt][nt][half * 2 + 0]; v.y = acc[mt][nt][half * 2 + 1];
                *(float2*)&Cs[r][cl] = v;
            }
        }
    if (sSum && tid < 128) { red0[tid] = 0.f; red1[tid] = 0.f; }
    __syncthreads();

    float4 bias = make_float4(0.f, 0.f, 0.f, 0.f);
    if (cBias) bias = *(const float4*)(cBias + bn + lane * 4);
    float psum[4] = {0.f, 0.f, 0.f, 0.f}, psq[4] = {0.f, 0.f, 0.f, 0.f};

#pragma unroll
    for (int i = 0; i < 16; i++) {
        int r = warp * 16 + i;
        int R = bm + r;
        if (R < M) {
            float4 v = *(const float4*)&Cs[r][lane * 4];
            v.x += bias.x; v.y += bias.y; v.z += bias.z; v.w += bias.w;
            *(float4*)(C + (size_t)R * NC + bn + lane * 4) = v;
            psum[0] += v.x; psum[1] += v.y; psum[2] += v.z; psum[3] += v.w;
            psq[0] += v.x * v.x; psq[1] += v.y * v.y;
            psq[2] += v.z * v.z; psq[3] += v.w * v.w;
        }
    }

    if (sSum) {
        __syncthreads();
#pragma unroll
        for (int j = 0; j < 4; j++) {
            atomicAdd(&red0[lane * 4 + j], psum[j]);
            atomicAdd(&red1[lane * 4 + j], psq[j]);
        }
        __syncthreads();
        if (tid < 128) {
            atomicAdd(&sSum[bn + tid], red0[tid]);
            atomicAdd(&sSq [bn + tid], red1[tid]);
        }
    }
}

// ---------------- pipelined edge message kernel (64-row tiles) -----------------
// MSG[e] = edge_rep[e]@W3 + edge_attr[e]@We + be + P[src[e]] + Q[dst[e]], + stats
__global__ void __launch_bounds__(256, 3) edge_msg_kernel(
    const float* __restrict__ edge_rep, const float* __restrict__ edge_attr,
    const int* __restrict__ src, const int* __restrict__ dst,
    const float* __restrict__ be)
{
    float    (*As)[64][36]  = reinterpret_cast<float(*)[64][36]>(smem_raw);
    unsigned (*Bs)[32][136] = reinterpret_cast<unsigned(*)[32][136]>(smem_raw + E_AS_BYTES);
    float    (*Cs)[132]     = reinterpret_cast<float(*)[132]>(smem_raw);   // overlay
    float* red0 = (float*)(smem_raw + E_PIPE);
    float* red1 = red0 + 128;

    const int tid = threadIdx.x, lane = tid & 31, warp = tid >> 5;
    const int wm = (warp & 1) * 32, wn = (warp >> 1) * 32;
    const size_t bm = (size_t)blockIdx.x * 64;

    const uint32_t AsAddr = s2u(smem_raw);
    const uint32_t BsAddr = AsAddr + E_AS_BYTES;
    const unsigned* Wu = g_Wbuf + OFF_EDGE;

    // L2 prefetch of the P/Q gather rows (hidden behind mainloop)
    if (tid < 128) {
        int e0 = (int)bm + (tid >> 1);
        const float* row = (tid & 1) ? (g_PQ + (size_t)dst[e0] * 256 + 128)
                                     : (g_PQ + (size_t)src[e0] * 256);
#pragma unroll
        for (int j = 0; j < 4; j++)
            asm volatile("prefetch.global.L2 [%0];" :: "l"(row + j * 32));
    }

    auto issue_copy = [&](int t) {
        const int s = t & 1;
        if (t < 4) {
            const int k0 = t * 32;
#pragma unroll
            for (int l = 0; l < 2; l++) {
                int c = tid + l * 256;
                int row = c >> 3, cc = c & 7;
                const float* sp = edge_rep + (bm + row) * HDIM + k0 + cc * 4;
                uint32_t dp = AsAddr + (uint32_t)(s * E_AS_STAGE + (row * 36 + cc * 4) * 4);
                cp16(dp, sp, true);
            }
#pragma unroll
            for (int l = 0; l < 4; l++) {
                int c = tid + l * 256;
                int row = c >> 5, cc = c & 31;
                const unsigned* sp = Wu + (size_t)(k0 + row) * HDIM + cc * 4;
                uint32_t dp = BsAddr + (uint32_t)(s * E_BS_STAGE + (row * 136 + cc * 4) * 4);
                cp16(dp, sp, true);
            }
        } else {
            // edge encoder tail: K=16
            {
                int row = tid >> 2, cc = tid & 3;
                const float* sp = edge_attr + (bm + row) * EDIM + cc * 4;
                uint32_t dp = AsAddr + (uint32_t)(s * E_AS_STAGE + (row * 36 + cc * 4) * 4);
                cp16(dp, sp, true);
            }
#pragma unroll
            for (int l = 0; l < 2; l++) {
                int c = tid + l * 256;
                int row = c >> 5, cc = c & 31;
                const unsigned* sp = Wu + (size_t)(128 + row) * HDIM + cc * 4;
                uint32_t dp = BsAddr + (uint32_t)(s * E_BS_STAGE + (row * 136 + cc * 4) * 4);
                cp16(dp, sp, true);
            }
        }
        cp_commit();
    };

    float acc[2][4][4];
#pragma unroll
    for (int mt = 0; mt < 2; mt++)
#pragma unroll
        for (int nt = 0; nt < 4; nt++)
#pragma unroll
            for (int i = 0; i < 4; i++) acc[mt][nt][i] = 0.f;

    issue_copy(0);

    for (int t = 0; t < 5; t++) {
        cp_wait<0>();
        __syncthreads();
        if (t + 1 < 5) issue_copy(t + 1);
        const int s = t & 1;
        const int qmax = (t < 4) ? 4 : 2;
        for (int q = 0; q < qmax; q++) {
            const int kr = q * 8 + (lane & 3);
            unsigned af[2][4], bf[4][2];
#pragma unroll
            for (int mt = 0; mt < 2; mt++) {
                int m = wm + mt * 16 + (lane >> 2);
                af[mt][0] = f2tf32(As[s][m][kr]);
                af[mt][1] = f2tf32(As[s][m + 8][kr]);
                af[mt][2] = f2tf32(As[s][m][kr + 4]);
                af[mt][3] = f2tf32(As[s][m + 8][kr + 4]);
            }
#pragma unroll
            for (int nt = 0; nt < 4; nt++) {
                int n = wn + nt * 8 + (lane >> 2);
                bf[nt][0] = Bs[s][kr][n];
                bf[nt][1] = Bs[s][kr + 4][n];
            }
#pragma unroll
            for (int mt = 0; mt < 2; mt++)
#pragma unroll
                for (int nt = 0; nt < 4; nt++)
                    mma_tf32(acc[mt][nt], af[mt], bf[nt]);
        }
        __syncthreads();
    }

    // ---------------- epilogue: stage -> smem, warp-per-edge coalesced ---------
#pragma unroll
    for (int mt = 0; mt < 2; mt++)
#pragma unroll
        for (int half = 0; half < 2; half++) {
            int r = wm + mt * 16 + (lane >> 2) + half * 8;
#pragma unroll
            for (int nt = 0; nt < 4; nt++) {
                int cl = wn + nt * 8 + 2 * (lane & 3);
                float2 v; v.x = acc[mt][nt][half * 2 + 0]; v.y = acc[mt][nt][half * 2 + 1];
                *(float2*)&Cs[r][cl] = v;
            }
        }
    if (tid < 128) { red0[tid] = 0.f; red1[tid] = 0.f; }
    __syncthreads();

    float4 bev = *(const float4*)(be + lane * 4);
    float psum[4] = {0.f, 0.f, 0.f, 0.f}, psq[4] = {0.f, 0.f, 0.f, 0.f};

#pragma unroll
    for (int i = 0; i < 8; i++) {
        int r = warp * 8 + i;
        size_t e = bm + r;
        int s = src[e], d = dst[e];
        float4 pv = *(const float4*)(g_PQ + (size_t)s * 256 + lane * 4);
        float4 qv = *(const float4*)(g_PQ + (size_t)d * 256 + 128 + lane * 4);
        float4 v = *(const float4*)&Cs[r][lane * 4];
        v.x += pv.x + qv.x + bev.x;
        v.y += pv.y + qv.y + bev.y;
        v.z += pv.z + qv.z + bev.z;
        v.w += pv.w + qv.w + bev.w;
        *(float4*)(g_MSG + e * HDIM + lane * 4) = v;
        psum[0] += v.x; psum[1] += v.y; psum[2] += v.z; psum[3] += v.w;
        psq[0] += v.x * v.x; psq[1] += v.y * v.y;
        psq[2] += v.z * v.z; psq[3] += v.w * v.w;
    }

    __syncthreads();
#pragma unroll
    for (int j = 0; j < 4; j++) {
        atomicAdd(&red0[lane * 4 + j], psum[j]);
        atomicAdd(&red1[lane * 4 + j], psq[j]);
    }
    __syncthreads();
    if (tid < 128) {
        atomicAdd(&g_sum[tid], red0[tid]);
        atomicAdd(&g_sq [tid], red1[tid]);
    }
}

// ---------------- BN+ReLU+scatter with vector red ------------------------------
__global__ void scatter_kernel(const int* __restrict__ dst) {
    unsigned t = blockIdx.x * blockDim.x + threadIdx.x;
    size_t e = (size_t)(t >> 5);
    int c4 = (t & 31) * 4;
    if (e < (size_t)N_EDGES) {
        int d = dst[e];
        float4 m = *(const float4*)(g_MSG + e * HDIM + c4);
        float v0 = fmaxf(fmaf(m.x, g_scaleArr[c4 + 0], g_shiftArr[c4 + 0]), 0.f);
        float v1 = fmaxf(fmaf(m.y, g_scaleArr[c4 + 1], g_shiftArr[c4 + 1]), 0.f);
        float v2 = fmaxf(fmaf(m.z, g_scaleArr[c4 + 2], g_shiftArr[c4 + 2]), 0.f);
        float v3 = fmaxf(fmaf(m.w, g_scaleArr[c4 + 3], g_shiftArr[c4 + 3]), 0.f);
        float* p = g_Y + (size_t)d * HDIM + c4;
        asm volatile("red.global.add.v4.f32 [%0], {%1,%2,%3,%4};"
                     :: "l"(p), "f"(v0), "f"(v1), "f"(v2), "f"(v3) : "memory");
    }
}

// ---------------- launch ------------------------------------------------------
extern "C" void kernel_launch(void* const* d_in, const int* in_sizes, int n_in,
                              void* d_out, int out_size) {
    const float* node_rep  = (const float*)d_in[0];
    const float* edge_rep  = (const float*)d_in[1];
    const float* edge_attr = (const float*)d_in[2];
    const int*   eidx      = (const int*)d_in[3];
    const float* W1  = (const float*)d_in[4];
    const float* W2  = (const float*)d_in[5];
    const float* W3  = (const float*)d_in[6];
    const float* We  = (const float*)d_in[7];
    const float* be  = (const float*)d_in[8];
    const float* bng = (const float*)d_in[9];
    const float* bnb = (const float*)d_in[10];
    const float* Wm1 = (const float*)d_in[11];
    const float* g1  = (const float*)d_in[12];
    const float* b1  = (const float*)d_in[13];
    const float* Wm2 = (const float*)d_in[14];
    const float* g2  = (const float*)d_in[15];
    const float* b2  = (const float*)d_in[16];
    const float* Wm3 = (const float*)d_in[17];
    const float* bm3 = (const float*)d_in[18];
    float* out = (float*)d_out;

    const int* src = eidx;
    const int* dst = eidx + N_EDGES;

    float *PQ, *Y, *H1, *H2, *SUM, *SQ, *SCALE, *SHIFT;
    unsigned* WB;
    cudaGetSymbolAddress((void**)&PQ, g_PQ);
    cudaGetSymbolAddress((void**)&Y,  g_Y);
    cudaGetSymbolAddress((void**)&H1, g_H1);
    cudaGetSymbolAddress((void**)&H2, g_H2);
    cudaGetSymbolAddress((void**)&SUM,   g_sum);
    cudaGetSymbolAddress((void**)&SQ,    g_sq);
    cudaGetSymbolAddress((void**)&SCALE, g_scaleArr);
    cudaGetSymbolAddress((void**)&SHIFT, g_shiftArr);
    cudaGetSymbolAddress((void**)&WB, g_Wbuf);

    const int GEMM_SMEM = G_PIPE + 2048 + 1024;   // 110592
    const int EDGE_SMEM = E_PIPE + 1024;          // 54272
    cudaFuncSetAttribute(gemm_mma_kernel, cudaFuncAttributeMaxDynamicSharedMemorySize, GEMM_SMEM);
    cudaFuncSetAttribute(edge_msg_kernel, cudaFuncAttributeMaxDynamicSharedMemorySize, EDGE_SMEM);

    const int MBLK = (N_NODES + 127) / 128;  // 782

    prep_kernel<<<(W_TOTAL + 255) / 256, 256>>>(W1, W2, W3, We, Wm1, Wm2, Wm3);
    zero_y_stats_kernel<<<4096, 256>>>();

    // fused node linears: PQ = node_rep @ [W1|W2]   (grid: col-blocks adjacent)
    gemm_mma_kernel<<<dim3(2, MBLK), 256, GEMM_SMEM>>>(
        node_rep, WB + OFF_NODE, PQ, N_NODES, HDIM, 256,
        nullptr, nullptr, nullptr, nullptr, nullptr);

    // edge GEMM + encoder + gathers + BN stats
    edge_msg_kernel<<<N_EDGES / 64, 256, EDGE_SMEM>>>(edge_rep, edge_attr, src, dst, be);

    bn_finalize_kernel<<<1, 128>>>(bng, bnb, 0, 128, 1.f / (float)N_EDGES);

    // BN + ReLU + scatter-sum
    scatter_kernel<<<(N_EDGES * 32) / 256, 256>>>(dst);

    // MLP layer 1
    gemm_mma_kernel<<<dim3(2, MBLK), 256, GEMM_SMEM>>>(
        Y, WB + OFF_M1, H1, N_NODES, HDIM, H2DIM,
        nullptr, nullptr, nullptr, SUM + 128, SQ + 128);
    bn_finalize_kernel<<<2, 128>>>(g1, b1, 128, 256, 1.f / (float)N_NODES);

    // MLP layer 2
    gemm_mma_kernel<<<dim3(2, MBLK), 256, GEMM_SMEM>>>(
        H1, WB + OFF_M2, H2, N_NODES, H2DIM, H2DIM,
        SCALE + 128, SHIFT + 128, nullptr, SUM + 384, SQ + 384);
    bn_finalize_kernel<<<2, 128>>>(g2, b2, 384, 256, 1.f / (float)N_NODES);

    // MLP layer 3
    gemm_mma_kernel<<<dim3(1, MBLK), 256, GEMM_SMEM>>>(
        H2, WB + OFF_M3, out, N_NODES, H2DIM, HDIM,
        SCALE + 384, SHIFT + 384, bm3, nullptr, nullptr);
}

// round 8
// speedup vs baseline: 1.1366x; 1.0546x over previous
#include <cuda_runtime.h>
#include <cuda_fp16.h>
#include <cstdint>

#define N_NODES 100000
#define N_EDGES 640000
#define HDIM 128
#define H2DIM 256
#define EDIM 16

// ---------------- scratch (device globals) ------------------------------------
__device__ __half g_PQh [(size_t)N_NODES * 256];   // fp16: [0:128]=node@W1, [128:256]=node@W2
__device__ __half g_MSGh[(size_t)N_EDGES * HDIM];  // fp16 pre-BN messages
__device__ float  g_Y   [(size_t)N_NODES * HDIM];  // scatter target (fp32 accum)
__device__ float  g_H1  [(size_t)N_NODES * H2DIM];
__device__ float  g_H2  [(size_t)N_NODES * H2DIM];
// BN stat slots: [0,128)=msg, [128,384)=bn1, [384,640)=bn2
__device__ float g_sum[640];
__device__ float g_sq [640];
__device__ float g_scaleArr[640];
__device__ float g_shiftArr[640];

// packed tf32 weights
#define OFF_NODE 0        // [128][256]  W1 | W2
#define OFF_EDGE 32768    // [144][128]  W3 rows 0..127, We rows 128..143
#define OFF_M1   51200    // [128][256]
#define OFF_M2   83968    // [256][256]
#define OFF_M3   149504   // [256][128]
#define W_TOTAL  182272
__device__ unsigned g_Wbuf[W_TOTAL];

// ---------------- helpers ------------------------------------------------------
__device__ __forceinline__ unsigned f2tf32(float x) {
    unsigned r;
    asm("cvt.rna.tf32.f32 %0, %1;" : "=r"(r) : "f"(x));
    return r;
}

__device__ __forceinline__ void mma_tf32(float* c, const unsigned* a, const unsigned* b) {
    asm volatile(
        "mma.sync.aligned.m16n8k8.row.col.f32.tf32.tf32.f32 "
        "{%0,%1,%2,%3}, {%4,%5,%6,%7}, {%8,%9}, {%0,%1,%2,%3};"
        : "+f"(c[0]), "+f"(c[1]), "+f"(c[2]), "+f"(c[3])
        : "r"(a[0]), "r"(a[1]), "r"(a[2]), "r"(a[3]), "r"(b[0]), "r"(b[1]));
}

__device__ __forceinline__ void cp16(uint32_t dst, const void* src, bool pred) {
    int sz = pred ? 16 : 0;
    asm volatile("cp.async.cg.shared.global [%0], [%1], 16, %2;"
                 :: "r"(dst), "l"(src), "r"(sz));
}
__device__ __forceinline__ void cp_commit() { asm volatile("cp.async.commit_group;"); }
template <int N> __device__ __forceinline__ void cp_wait() {
    asm volatile("cp.async.wait_group %0;" :: "n"(N));
}
__device__ __forceinline__ uint32_t s2u(const void* p) {
    uint32_t a;
    asm("{ .reg .u64 t; cvta.to.shared.u64 t, %1; cvt.u32.u64 %0, t; }" : "=r"(a) : "l"(p));
    return a;
}
__device__ __forceinline__ uint2 pack_half4(float4 v) {
    __half2 h0 = __floats2half2_rn(v.x, v.y);
    __half2 h1 = __floats2half2_rn(v.z, v.w);
    uint2 u;
    u.x = *(unsigned*)&h0;
    u.y = *(unsigned*)&h1;
    return u;
}
__device__ __forceinline__ float4 unpack_half4(uint2 u) {
    __half2 h0 = *(__half2*)&u.x;
    __half2 h1 = *(__half2*)&u.y;
    float2 f0 = __half22float2(h0);
    float2 f1 = __half22float2(h1);
    return make_float4(f0.x, f0.y, f1.x, f1.y);
}

// GEMM smem geometry (128-row A tile, 3 stages)
#define G_AS_STAGE 18432             // 128*36*4
#define G_BS_STAGE 17408             // 32*136*4
#define G_AS_BYTES (3 * G_AS_STAGE)  // 55296
#define G_BS_BYTES (3 * G_BS_STAGE)  // 52224
#define G_PIPE (G_AS_BYTES + G_BS_BYTES)  // 107520
// edge smem geometry (64-row A tile, 2 stages)
#define E_AS_STAGE 9216              // 64*36*4
#define E_BS_STAGE 17408
#define E_AS_BYTES (2 * E_AS_STAGE)  // 18432
#define E_BS_BYTES (2 * E_BS_STAGE)  // 34816
#define E_PIPE (E_AS_BYTES + E_BS_BYTES)  // 53248

// ---------------- utility kernels ----------------------------------------------
__global__ void prep_kernel(const float* __restrict__ W1, const float* __restrict__ W2,
                            const float* __restrict__ W3, const float* __restrict__ We,
                            const float* __restrict__ Wm1, const float* __restrict__ Wm2,
                            const float* __restrict__ Wm3) {
    int i = blockIdx.x * blockDim.x + threadIdx.x;
    if (i < 32768) {
        int k = i >> 8, n = i & 255;
        float v = (n < 128) ? W1[k * 128 + n] : W2[k * 128 + (n - 128)];
        g_Wbuf[OFF_NODE + i] = f2tf32(v);
    } else if (i < 51200) {
        int j = i - 32768;
        float v = (j < 128 * 128) ? W3[j] : We[j - 128 * 128];
        g_Wbuf[OFF_EDGE + j] = f2tf32(v);
    } else if (i < 83968) {
        g_Wbuf[OFF_M1 + (i - 51200)] = f2tf32(Wm1[i - 51200]);
    } else if (i < 149504) {
        g_Wbuf[OFF_M2 + (i - 83968)] = f2tf32(Wm2[i - 83968]);
    } else if (i < W_TOTAL) {
        g_Wbuf[OFF_M3 + (i - 149504)] = f2tf32(Wm3[i - 149504]);
    }
}

__global__ void zero_y_stats_kernel() {
    size_t i = (size_t)blockIdx.x * blockDim.x + threadIdx.x;
    const size_t tot = (size_t)N_NODES * HDIM;
    const size_t stride = (size_t)gridDim.x * blockDim.x;
    for (size_t p = i; p < tot; p += stride) g_Y[p] = 0.f;
    if (i < 640) { g_sum[i] = 0.f; g_sq[i] = 0.f; }
}

__global__ void bn_finalize_kernel(const float* __restrict__ g,
                                   const float* __restrict__ b,
                                   int off, int cols, float invCnt) {
    int c = blockIdx.x * blockDim.x + threadIdx.x;
    if (c < cols) {
        float mean = g_sum[off + c] * invCnt;
        float var  = fmaxf(g_sq[off + c] * invCnt - mean * mean, 0.f);
        float a = g[c] * rsqrtf(var + 1e-5f);
        g_scaleArr[off + c] = a;
        g_shiftArr[off + c] = fmaf(-mean, a, b[c]);
    }
}

extern __shared__ char smem_raw[];

// ---------------- 3-stage pipelined tf32 GEMM with fused BN ---------------------
// C[M,NC] = act(A) @ Wu (+cBias); act = relu(aScale[k]*x+aShift[k]) if aScale.
// outHalf: store C as fp16 (used for the PQ node-linear output).
__global__ void __launch_bounds__(256, 2) gemm_mma_kernel(
    const float* __restrict__ A, const unsigned* __restrict__ Wu,
    void* __restrict__ Cout, int M, int K, int NC, int outHalf,
    const float* __restrict__ aScale, const float* __restrict__ aShift,
    const float* __restrict__ cBias,
    float* __restrict__ sSum, float* __restrict__ sSq)
{
    float    (*As)[128][36]  = reinterpret_cast<float(*)[128][36]>(smem_raw);
    unsigned (*Bs)[32][136]  = reinterpret_cast<unsigned(*)[32][136]>(smem_raw + G_AS_BYTES);
    float    (*Cs)[132]      = reinterpret_cast<float(*)[132]>(smem_raw);   // overlay
    float* scs  = (float*)(smem_raw + G_PIPE);          // 256
    float* shs  = scs + 256;                            // 256
    float* red0 = shs + 256;                            // 128
    float* red1 = red0 + 128;                           // 128

    const int tid = threadIdx.x, lane = tid & 31, warp = tid >> 5;
    const int wm = (warp & 3) * 32, wn = (warp >> 2) * 64;
    const int bm = blockIdx.y * 128, bn = blockIdx.x * 128;
    const bool useBN = (aScale != nullptr);

    const uint32_t AsAddr = s2u(smem_raw);
    const uint32_t BsAddr = AsAddr + G_AS_BYTES;

    if (useBN && tid < K) { scs[tid] = aScale[tid]; shs[tid] = aShift[tid]; }

    auto issue_copy = [&](int t) {
        const int s = t % 3;
        const int k0 = t * 32;
#pragma unroll
        for (int l = 0; l < 4; l++) {
            int c = tid + l * 256;
            int row = c >> 3, cc = c & 7;
            int grow = bm + row;
            const float* src = A + (size_t)grow * K + k0 + cc * 4;
            uint32_t dst = AsAddr + (uint32_t)(s * G_AS_STAGE + (row * 36 + cc * 4) * 4);
            cp16(dst, src, grow < M);
        }
#pragma unroll
        for (int l = 0; l < 4; l++) {
            int c = tid + l * 256;
            int row = c >> 5, cc = c & 31;
            const unsigned* src = Wu + (size_t)(k0 + row) * NC + bn + cc * 4;
            uint32_t dst = BsAddr + (uint32_t)(s * G_BS_STAGE + (row * 136 + cc * 4) * 4);
            cp16(dst, src, true);
        }
        cp_commit();
    };

    float acc[2][8][4];
#pragma unroll
    for (int mt = 0; mt < 2; mt++)
#pragma unroll
        for (int nt = 0; nt < 8; nt++)
#pragma unroll
            for (int i = 0; i < 4; i++) acc[mt][nt][i] = 0.f;

    const int T = K >> 5;
    issue_copy(0);
    if (T > 1) issue_copy(1);

    for (int t = 0; t < T; t++) {
        if (t + 2 < T)      { issue_copy(t + 2); cp_wait<2>(); }
        else if (t + 1 < T) { cp_wait<1>(); }
        else                { cp_wait<0>(); }
        __syncthreads();
        const int s = t % 3;
        const int k0 = t * 32;
#pragma unroll
        for (int q = 0; q < 4; q++) {
            const int kr = q * 8 + (lane & 3);
            float s0 = 1.f, h0 = 0.f, s4 = 1.f, h4 = 0.f;
            if (useBN) {
                s0 = scs[k0 + kr];     h0 = shs[k0 + kr];
                s4 = scs[k0 + kr + 4]; h4 = shs[k0 + kr + 4];
            }
            unsigned af[2][4], bf[8][2];
#pragma unroll
            for (int mt = 0; mt < 2; mt++) {
                int m = wm + mt * 16 + (lane >> 2);
                float a0 = As[s][m][kr],     a1 = As[s][m + 8][kr];
                float a2 = As[s][m][kr + 4], a3 = As[s][m + 8][kr + 4];
                if (useBN) {
                    a0 = fmaxf(fmaf(a0, s0, h0), 0.f);
                    a1 = fmaxf(fmaf(a1, s0, h0), 0.f);
                    a2 = fmaxf(fmaf(a2, s4, h4), 0.f);
                    a3 = fmaxf(fmaf(a3, s4, h4), 0.f);
                }
                af[mt][0] = f2tf32(a0); af[mt][1] = f2tf32(a1);
                af[mt][2] = f2tf32(a2); af[mt][3] = f2tf32(a3);
            }
#pragma unroll
            for (int nt = 0; nt < 8; nt++) {
                int n = wn + nt * 8 + (lane >> 2);
                bf[nt][0] = Bs[s][kr][n];
                bf[nt][1] = Bs[s][kr + 4][n];
            }
#pragma unroll
            for (int mt = 0; mt < 2; mt++)
#pragma unroll
                for (int nt = 0; nt < 8; nt++)
                    mma_tf32(acc[mt][nt], af[mt], bf[nt]);
        }
        __syncthreads();
    }

    // ---------------- epilogue: stage -> smem, warp-per-row coalesced ----------
#pragma unroll
    for (int mt = 0; mt < 2; mt++)
#pragma unroll
        for (int half = 0; half < 2; half++) {
            int r = wm + mt * 16 + (lane >> 2) + half * 8;
#pragma unroll
            for (int nt = 0; nt < 8; nt++) {
                int cl = wn + nt * 8 + 2 * (lane & 3);
                float2 v; v.x = acc[mt][nt][half * 2 + 0]; v.y = acc[mt][nt][half * 2 + 1];
                *(float2*)&Cs[r][cl] = v;
            }
        }
    if (sSum && tid < 128) { red0[tid] = 0.f; red1[tid] = 0.f; }
    __syncthreads();

    float4 bias = make_float4(0.f, 0.f, 0.f, 0.f);
    if (cBias) bias = *(const float4*)(cBias + bn + lane * 4);
    float psum[4] = {0.f, 0.f, 0.f, 0.f}, psq[4] = {0.f, 0.f, 0.f, 0.f};

#pragma unroll
    for (int i = 0; i < 16; i++) {
        int r = warp * 16 + i;
        int R = bm + r;
        if (R < M) {
            float4 v = *(const float4*)&Cs[r][lane * 4];
            v.x += bias.x; v.y += bias.y; v.z += bias.z; v.w += bias.w;
            if (outHalf) {
                __half* Ch = (__half*)Cout;
                *(uint2*)(Ch + (size_t)R * NC + bn + lane * 4) = pack_half4(v);
            } else {
                float* Cf = (float*)Cout;
                *(float4*)(Cf + (size_t)R * NC + bn + lane * 4) = v;
            }
            psum[0] += v.x; psum[1] += v.y; psum[2] += v.z; psum[3] += v.w;
            psq[0] += v.x * v.x; psq[1] += v.y * v.y;
            psq[2] += v.z * v.z; psq[3] += v.w * v.w;
        }
    }

    if (sSum) {
        __syncthreads();
#pragma unroll
        for (int j = 0; j < 4; j++) {
            atomicAdd(&red0[lane * 4 + j], psum[j]);
            atomicAdd(&red1[lane * 4 + j], psq[j]);
        }
        __syncthreads();
        if (tid < 128) {
            atomicAdd(&sSum[bn + tid], red0[tid]);
            atomicAdd(&sSq [bn + tid], red1[tid]);
        }
    }
}

// ---------------- pipelined edge message kernel (64-row tiles) -----------------
// MSG[e] = edge_rep[e]@W3 + edge_attr[e]@We + be + P[src[e]] + Q[dst[e]], + stats
// PQ and MSG are fp16 (PQ working set 51MB -> L2-resident).
__global__ void __launch_bounds__(256, 3) edge_msg_kernel(
    const float* __restrict__ edge_rep, const float* __restrict__ edge_attr,
    const int* __restrict__ src, const int* __restrict__ dst,
    const float* __restrict__ be)
{
    float    (*As)[64][36]  = reinterpret_cast<float(*)[64][36]>(smem_raw);
    unsigned (*Bs)[32][136] = reinterpret_cast<unsigned(*)[32][136]>(smem_raw + E_AS_BYTES);
    float    (*Cs)[132]     = reinterpret_cast<float(*)[132]>(smem_raw);   // overlay
    float* red0 = (float*)(smem_raw + E_PIPE);
    float* red1 = red0 + 128;

    const int tid = threadIdx.x, lane = tid & 31, warp = tid >> 5;
    const int wm = (warp & 1) * 32, wn = (warp >> 1) * 32;
    const size_t bm = (size_t)blockIdx.x * 64;

    const uint32_t AsAddr = s2u(smem_raw);
    const uint32_t BsAddr = AsAddr + E_AS_BYTES;
    const unsigned* Wu = g_Wbuf + OFF_EDGE;

    // L2 prefetch of the P/Q gather rows (hidden behind mainloop)
    if (tid < 128) {
        int e0 = (int)bm + (tid >> 1);
        const __half* row = (tid & 1) ? (g_PQh + (size_t)dst[e0] * 256 + 128)
                                      : (g_PQh + (size_t)src[e0] * 256);
        asm volatile("prefetch.global.L2 [%0];" :: "l"(row));
        asm volatile("prefetch.global.L2 [%0];" :: "l"(row + 64));
    }

    auto issue_copy = [&](int t) {
        const int s = t & 1;
        if (t < 4) {
            const int k0 = t * 32;
#pragma unroll
            for (int l = 0; l < 2; l++) {
                int c = tid + l * 256;
                int row = c >> 3, cc = c & 7;
                const float* sp = edge_rep + (bm + row) * HDIM + k0 + cc * 4;
                uint32_t dp = AsAddr + (uint32_t)(s * E_AS_STAGE + (row * 36 + cc * 4) * 4);
                cp16(dp, sp, true);
            }
#pragma unroll
            for (int l = 0; l < 4; l++) {
                int c = tid + l * 256;
                int row = c >> 5, cc = c & 31;
                const unsigned* sp = Wu + (size_t)(k0 + row) * HDIM + cc * 4;
                uint32_t dp = BsAddr + (uint32_t)(s * E_BS_STAGE + (row * 136 + cc * 4) * 4);
                cp16(dp, sp, true);
            }
        } else {
            // edge encoder tail: K=16
            {
                int row = tid >> 2, cc = tid & 3;
                const float* sp = edge_attr + (bm + row) * EDIM + cc * 4;
                uint32_t dp = AsAddr + (uint32_t)(s * E_AS_STAGE + (row * 36 + cc * 4) * 4);
                cp16(dp, sp, true);
            }
#pragma unroll
            for (int l = 0; l < 2; l++) {
                int c = tid + l * 256;
                int row = c >> 5, cc = c & 31;
                const unsigned* sp = Wu + (size_t)(128 + row) * HDIM + cc * 4;
                uint32_t dp = BsAddr + (uint32_t)(s * E_BS_STAGE + (row * 136 + cc * 4) * 4);
                cp16(dp, sp, true);
            }
        }
        cp_commit();
    };

    float acc[2][4][4];
#pragma unroll
    for (int mt = 0; mt < 2; mt++)
#pragma unroll
        for (int nt = 0; nt < 4; nt++)
#pragma unroll
            for (int i = 0; i < 4; i++) acc[mt][nt][i] = 0.f;

    issue_copy(0);

    for (int t = 0; t < 5; t++) {
        cp_wait<0>();
        __syncthreads();
        if (t + 1 < 5) issue_copy(t + 1);
        const int s = t & 1;
        const int qmax = (t < 4) ? 4 : 2;
        for (int q = 0; q < qmax; q++) {
            const int kr = q * 8 + (lane & 3);
            unsigned af[2][4], bf[4][2];
#pragma unroll
            for (int mt = 0; mt < 2; mt++) {
                int m = wm + mt * 16 + (lane >> 2);
                af[mt][0] = f2tf32(As[s][m][kr]);
                af[mt][1] = f2tf32(As[s][m + 8][kr]);
                af[mt][2] = f2tf32(As[s][m][kr + 4]);
                af[mt][3] = f2tf32(As[s][m + 8][kr + 4]);
            }
#pragma unroll
            for (int nt = 0; nt < 4; nt++) {
                int n = wn + nt * 8 + (lane >> 2);
                bf[nt][0] = Bs[s][kr][n];
                bf[nt][1] = Bs[s][kr + 4][n];
            }
#pragma unroll
            for (int mt = 0; mt < 2; mt++)
#pragma unroll
                for (int nt = 0; nt < 4; nt++)
                    mma_tf32(acc[mt][nt], af[mt], bf[nt]);
        }
        __syncthreads();
    }

    // ---------------- epilogue: stage -> smem, warp-per-edge coalesced ---------
#pragma unroll
    for (int mt = 0; mt < 2; mt++)
#pragma unroll
        for (int half = 0; half < 2; half++) {
            int r = wm + mt * 16 + (lane >> 2) + half * 8;
#pragma unroll
            for (int nt = 0; nt < 4; nt++) {
                int cl = wn + nt * 8 + 2 * (lane & 3);
                float2 v; v.x = acc[mt][nt][half * 2 + 0]; v.y = acc[mt][nt][half * 2 + 1];
                *(float2*)&Cs[r][cl] = v;
            }
        }
    if (tid < 128) { red0[tid] = 0.f; red1[tid] = 0.f; }
    __syncthreads();

    float4 bev = *(const float4*)(be + lane * 4);
    float psum[4] = {0.f, 0.f, 0.f, 0.f}, psq[4] = {0.f, 0.f, 0.f, 0.f};

#pragma unroll
    for (int i = 0; i < 8; i++) {
        int r = warp * 8 + i;
        size_t e = bm + r;
        int s = src[e], d = dst[e];
        float4 pv = unpack_half4(*(const uint2*)(g_PQh + (size_t)s * 256 + lane * 4));
        float4 qv = unpack_half4(*(const uint2*)(g_PQh + (size_t)d * 256 + 128 + lane * 4));
        float4 v = *(const float4*)&Cs[r][lane * 4];
        v.x += pv.x + qv.x + bev.x;
        v.y += pv.y + qv.y + bev.y;
        v.z += pv.z + qv.z + bev.z;
        v.w += pv.w + qv.w + bev.w;
        *(uint2*)(g_MSGh + e * HDIM + lane * 4) = pack_half4(v);
        psum[0] += v.x; psum[1] += v.y; psum[2] += v.z; psum[3] += v.w;
        psq[0] += v.x * v.x; psq[1] += v.y * v.y;
        psq[2] += v.z * v.z; psq[3] += v.w * v.w;
    }

    __syncthreads();
#pragma unroll
    for (int j = 0; j < 4; j++) {
        atomicAdd(&red0[lane * 4 + j], psum[j]);
        atomicAdd(&red1[lane * 4 + j], psq[j]);
    }
    __syncthreads();
    if (tid < 128) {
        atomicAdd(&g_sum[tid], red0[tid]);
        atomicAdd(&g_sq [tid], red1[tid]);
    }
}

// ---------------- BN+ReLU+scatter with vector red ------------------------------
__global__ void scatter_kernel(const int* __restrict__ dst) {
    unsigned t = blockIdx.x * blockDim.x + threadIdx.x;
    size_t e = (size_t)(t >> 5);
    int c4 = (t & 31) * 4;
    if (e < (size_t)N_EDGES) {
        int d = dst[e];
        float4 m = unpack_half4(*(const uint2*)(g_MSGh + e * HDIM + c4));
        float v0 = fmaxf(fmaf(m.x, g_scaleArr[c4 + 0], g_shiftArr[c4 + 0]), 0.f);
        float v1 = fmaxf(fmaf(m.y, g_scaleArr[c4 + 1], g_shiftArr[c4 + 1]), 0.f);
        float v2 = fmaxf(fmaf(m.z, g_scaleArr[c4 + 2], g_shiftArr[c4 + 2]), 0.f);
        float v3 = fmaxf(fmaf(m.w, g_scaleArr[c4 + 3], g_shiftArr[c4 + 3]), 0.f);
        float* p = g_Y + (size_t)d * HDIM + c4;
        asm volatile("red.global.add.v4.f32 [%0], {%1,%2,%3,%4};"
                     :: "l"(p), "f"(v0), "f"(v1), "f"(v2), "f"(v3) : "memory");
    }
}

// ---------------- launch ------------------------------------------------------
extern "C" void kernel_launch(void* const* d_in, const int* in_sizes, int n_in,
                              void* d_out, int out_size) {
    const float* node_rep  = (const float*)d_in[0];
    const float* edge_rep  = (const float*)d_in[1];
    const float* edge_attr = (const float*)d_in[2];
    const int*   eidx      = (const int*)d_in[3];
    const float* W1  = (const float*)d_in[4];
    const float* W2  = (const float*)d_in[5];
    const float* W3  = (const float*)d_in[6];
    const float* We  = (const float*)d_in[7];
    const float* be  = (const float*)d_in[8];
    const float* bng = (const float*)d_in[9];
    const float* bnb = (const float*)d_in[10];
    const float* Wm1 = (const float*)d_in[11];
    const float* g1  = (const float*)d_in[12];
    const float* b1  = (const float*)d_in[13];
    const float* Wm2 = (const float*)d_in[14];
    const float* g2  = (const float*)d_in[15];
    const float* b2  = (const float*)d_in[16];
    const float* Wm3 = (const float*)d_in[17];
    const float* bm3 = (const float*)d_in[18];
    float* out = (float*)d_out;

    const int* src = eidx;
    const int* dst = eidx + N_EDGES;

    float *Y, *H1, *H2, *SUM, *SQ, *SCALE, *SHIFT;
    __half* PQh;
    unsigned* WB;
    cudaGetSymbolAddress((void**)&PQh, g_PQh);
    cudaGetSymbolAddress((void**)&Y,  g_Y);
    cudaGetSymbolAddress((void**)&H1, g_H1);
    cudaGetSymbolAddress((void**)&H2, g_H2);
    cudaGetSymbolAddress((void**)&SUM,   g_sum);
    cudaGetSymbolAddress((void**)&SQ,    g_sq);
    cudaGetSymbolAddress((void**)&SCALE, g_scaleArr);
    cudaGetSymbolAddress((void**)&SHIFT, g_shiftArr);
    cudaGetSymbolAddress((void**)&WB, g_Wbuf);

    const int GEMM_SMEM = G_PIPE + 2048 + 1024;   // 110592
    const int EDGE_SMEM = E_PIPE + 1024;          // 54272
    cudaFuncSetAttribute(gemm_mma_kernel, cudaFuncAttributeMaxDynamicSharedMemorySize, GEMM_SMEM);
    cudaFuncSetAttribute(edge_msg_kernel, cudaFuncAttributeMaxDynamicSharedMemorySize, EDGE_SMEM);

    const int MBLK = (N_NODES + 127) / 128;  // 782

    prep_kernel<<<(W_TOTAL + 255) / 256, 256>>>(W1, W2, W3, We, Wm1, Wm2, Wm3);
    zero_y_stats_kernel<<<4096, 256>>>();

    // fused node linears: PQ = node_rep @ [W1|W2] -> fp16
    gemm_mma_kernel<<<dim3(2, MBLK), 256, GEMM_SMEM>>>(
        node_rep, WB + OFF_NODE, PQh, N_NODES, HDIM, 256, 1,
        nullptr, nullptr, nullptr, nullptr, nullptr);

    // edge GEMM + encoder + gathers + BN stats
    edge_msg_kernel<<<N_EDGES / 64, 256, EDGE_SMEM>>>(edge_rep, edge_attr, src, dst, be);

    bn_finalize_kernel<<<1, 128>>>(bng, bnb, 0, 128, 1.f / (float)N_EDGES);

    // BN + ReLU + scatter-sum
    scatter_kernel<<<(N_EDGES * 32) / 256, 256>>>(dst);

    // MLP layer 1
    gemm_mma_kernel<<<dim3(2, MBLK), 256, GEMM_SMEM>>>(
        Y, WB + OFF_M1, H1, N_NODES, HDIM, H2DIM, 0,
        nullptr, nullptr, nullptr, SUM + 128, SQ + 128);
    bn_finalize_kernel<<<2, 128>>>(g1, b1, 128, 256, 1.f / (float)N_NODES);

    // MLP layer 2
    gemm_mma_kernel<<<dim3(2, MBLK), 256, GEMM_SMEM>>>(
        H1, WB + OFF_M2, H2, N_NODES, H2DIM, H2DIM, 0,
        SCALE + 128, SHIFT + 128, nullptr, SUM + 384, SQ + 384);
    bn_finalize_kernel<<<2, 128>>>(g2, b2, 384, 256, 1.f / (float)N_NODES);

    // MLP layer 3
    gemm_mma_kernel<<<dim3(1, MBLK), 256, GEMM_SMEM>>>(
        H2, WB + OFF_M3, out, N_NODES, H2DIM, HDIM, 0,
        SCALE + 384, SHIFT + 384, bm3, nullptr, nullptr);
}

// round 10
// speedup vs baseline: 1.1497x; 1.0115x over previous
#include <cuda_runtime.h>
#include <cuda_fp16.h>
#include <cstdint>

#define N_NODES 100000
#define N_EDGES 640000
#define HDIM 128
#define H2DIM 256
#define EDIM 16

// ---------------- scratch (device globals) ------------------------------------
__device__ __half g_PQh [(size_t)N_NODES * 256];   // fp16: [0:128]=node@W1, [128:256]=node@W2
__device__ __half g_MSGh[(size_t)N_EDGES * HDIM];  // fp16 pre-BN messages
__device__ float  g_Y   [(size_t)N_NODES * HDIM];  // scatter target (fp32 accum)
__device__ __half g_H1h [(size_t)N_NODES * H2DIM]; // fp16 MLP intermediates
__device__ __half g_H2h [(size_t)N_NODES * H2DIM];
// BN stat slots: [0,128)=msg, [128,384)=bn1, [384,640)=bn2
__device__ float g_sum[640];
__device__ float g_sq [640];
__device__ float g_scaleArr[640];
__device__ float g_shiftArr[640];

// packed tf32 weights
#define OFF_NODE 0        // [128][256]  W1 | W2
#define OFF_EDGE 32768    // [144][128]  W3 rows 0..127, We rows 128..143
#define OFF_M1   51200    // [128][256]
#define OFF_M2   83968    // [256][256]
#define OFF_M3   149504   // [256][128]
#define W_TOTAL  182272
__device__ unsigned g_Wbuf[W_TOTAL];

// ---------------- helpers ------------------------------------------------------
__device__ __forceinline__ unsigned f2tf32(float x) {
    unsigned r;
    asm("cvt.rna.tf32.f32 %0, %1;" : "=r"(r) : "f"(x));
    return r;
}

__device__ __forceinline__ void mma_tf32(float* c, const unsigned* a, const unsigned* b) {
    asm volatile(
        "mma.sync.aligned.m16n8k8.row.col.f32.tf32.tf32.f32 "
        "{%0,%1,%2,%3}, {%4,%5,%6,%7}, {%8,%9}, {%0,%1,%2,%3};"
        : "+f"(c[0]), "+f"(c[1]), "+f"(c[2]), "+f"(c[3])
        : "r"(a[0]), "r"(a[1]), "r"(a[2]), "r"(a[3]), "r"(b[0]), "r"(b[1]));
}

__device__ __forceinline__ void cp16(uint32_t dst, const void* src, bool pred) {
    int sz = pred ? 16 : 0;
    asm volatile("cp.async.cg.shared.global [%0], [%1], 16, %2;"
                 :: "r"(dst), "l"(src), "r"(sz));
}
__device__ __forceinline__ void cp_commit() { asm volatile("cp.async.commit_group;"); }
template <int N> __device__ __forceinline__ void cp_wait() {
    asm volatile("cp.async.wait_group %0;" :: "n"(N));
}
__device__ __forceinline__ uint32_t s2u(const void* p) {
    uint32_t a;
    asm("{ .reg .u64 t; cvta.to.shared.u64 t, %1; cvt.u32.u64 %0, t; }" : "=r"(a) : "l"(p));
    return a;
}
__device__ __forceinline__ uint2 pack_half4(float4 v) {
    __half2 h0 = __floats2half2_rn(v.x, v.y);
    __half2 h1 = __floats2half2_rn(v.z, v.w);
    uint2 u;
    u.x = *(unsigned*)&h0;
    u.y = *(unsigned*)&h1;
    return u;
}
__device__ __forceinline__ float4 unpack_half4(uint2 u) {
    __half2 h0 = *(__half2*)&u.x;
    __half2 h1 = *(__half2*)&u.y;
    float2 f0 = __half22float2(h0);
    float2 f1 = __half22float2(h1);
    return make_float4(f0.x, f0.y, f1.x, f1.y);
}
__device__ __forceinline__ float cvtA(float x)  { return x; }
__device__ __forceinline__ float cvtA(__half x) { return __half2float(x); }

// GEMM smem geometry: B stage fixed, 3 stages; A stride padded per type.
#define G_BS_STAGE 17408             // 32*136*4
#define G_BS_BYTES (3 * G_BS_STAGE)  // 52224
// edge smem geometry (64-row A tile, 2 stages)
#define E_AS_STAGE 9216              // 64*36*4
#define E_BS_STAGE 17408
#define E_AS_BYTES (2 * E_AS_STAGE)  // 18432
#define E_PIPE (E_AS_BYTES + 2 * E_BS_STAGE)  // 53248

// ---------------- utility kernels ----------------------------------------------
__global__ void prep_kernel(const float* __restrict__ W1, const float* __restrict__ W2,
                            const float* __restrict__ W3, const float* __restrict__ We,
                            const float* __restrict__ Wm1, const float* __restrict__ Wm2,
                            const float* __restrict__ Wm3) {
    int i = blockIdx.x * blockDim.x + threadIdx.x;
    if (i < 32768) {
        int k = i >> 8, n = i & 255;
        float v = (n < 128) ? W1[k * 128 + n] : W2[k * 128 + (n - 128)];
        g_Wbuf[OFF_NODE + i] = f2tf32(v);
    } else if (i < 51200) {
        int j = i - 32768;
        float v = (j < 128 * 128) ? W3[j] : We[j - 128 * 128];
        g_Wbuf[OFF_EDGE + j] = f2tf32(v);
    } else if (i < 83968) {
        g_Wbuf[OFF_M1 + (i - 51200)] = f2tf32(Wm1[i - 51200]);
    } else if (i < 149504) {
        g_Wbuf[OFF_M2 + (i - 83968)] = f2tf32(Wm2[i - 83968]);
    } else if (i < W_TOTAL) {
        g_Wbuf[OFF_M3 + (i - 149504)] = f2tf32(Wm3[i - 149504]);
    }
}

__global__ void zero_y_stats_kernel() {
    size_t i = (size_t)blockIdx.x * blockDim.x + threadIdx.x;
    const size_t tot = (size_t)N_NODES * HDIM;
    const size_t stride = (size_t)gridDim.x * blockDim.x;
    for (size_t p = i; p < tot; p += stride) g_Y[p] = 0.f;
    if (i < 640) { g_sum[i] = 0.f; g_sq[i] = 0.f; }
}

__global__ void bn_finalize_kernel(const float* __restrict__ g,
                                   const float* __restrict__ b,
                                   int off, int cols, float invCnt) {
    int c = blockIdx.x * blockDim.x + threadIdx.x;
    if (c < cols) {
        float mean = g_sum[off + c] * invCnt;
        float var  = fmaxf(g_sq[off + c] * invCnt - mean * mean, 0.f);
        float a = g[c] * rsqrtf(var + 1e-5f);
        g_scaleArr[off + c] = a;
        g_shiftArr[off + c] = fmaf(-mean, a, b[c]);
    }
}

extern __shared__ char smem_raw[];

// ---------------- 3-stage pipelined tf32 GEMM with fused BN ---------------------
// C[M,NC] = act(A) @ Wu (+cBias); act = relu(aScale[k]*x+aShift[k]) if aScale.
// AT = float or __half (A storage type). outHalf: store C as fp16.
// fp16 A rows padded to 40 halfs (80B, multiple of 16) for cp.async alignment.
template <typename AT>
__global__ void __launch_bounds__(256, 2) gemm_mma_kernel(
    const AT* __restrict__ A, const unsigned* __restrict__ Wu,
    void* __restrict__ Cout, int M, int K, int NC, int outHalf,
    const float* __restrict__ aScale, const float* __restrict__ aShift,
    const float* __restrict__ cBias,
    float* __restrict__ sSum, float* __restrict__ sSq)
{
    constexpr int ASTR       = (sizeof(AT) == 4) ? 36 : 40;   // row stride in elements
    constexpr int AS_STAGE_B = 128 * ASTR * (int)sizeof(AT);  // 18432 / 10240
    constexpr int AS_BYTES   = 3 * AS_STAGE_B;
    constexpr int PIPE       = AS_BYTES + G_BS_BYTES;

    AT       (*As)[128][ASTR] = reinterpret_cast<AT(*)[128][ASTR]>(smem_raw);
    unsigned (*Bs)[32][136]   = reinterpret_cast<unsigned(*)[32][136]>(smem_raw + AS_BYTES);
    float    (*Cs)[132]       = reinterpret_cast<float(*)[132]>(smem_raw);   // overlay
    float* scs  = (float*)(smem_raw + PIPE);            // 256
    float* shs  = scs + 256;                            // 256
    float* red0 = shs + 256;                            // 128
    float* red1 = red0 + 128;                           // 128

    const int tid = threadIdx.x, lane = tid & 31, warp = tid >> 5;
    const int wm = (warp & 3) * 32, wn = (warp >> 2) * 64;
    const int bm = blockIdx.y * 128, bn = blockIdx.x * 128;
    const bool useBN = (aScale != nullptr);

    const uint32_t AsAddr = s2u(smem_raw);
    const uint32_t BsAddr = AsAddr + AS_BYTES;

    if (useBN && tid < K) { scs[tid] = aScale[tid]; shs[tid] = aShift[tid]; }

    auto issue_copy = [&](int t) {
        const int s = t % 3;
        const int k0 = t * 32;
        if constexpr (sizeof(AT) == 4) {
#pragma unroll
            for (int l = 0; l < 4; l++) {
                int c = tid + l * 256;
                int row = c >> 3, cc = c & 7;
                int grow = bm + row;
                const AT* src = A + (size_t)grow * K + k0 + cc * 4;
                uint32_t dst = AsAddr + (uint32_t)(s * AS_STAGE_B + (row * ASTR + cc * 4) * 4);
                cp16(dst, src, grow < M);
            }
        } else {
#pragma unroll
            for (int l = 0; l < 2; l++) {
                int c = tid + l * 256;
                int row = c >> 2, cc = c & 3;
                int grow = bm + row;
                const AT* src = A + (size_t)grow * K + k0 + cc * 8;
                // (row*40 + cc*8)*2 bytes: row*80 + cc*16 -> 16B aligned
                uint32_t dst = AsAddr + (uint32_t)(s * AS_STAGE_B + (row * ASTR + cc * 8) * 2);
                cp16(dst, src, grow < M);
            }
        }
#pragma unroll
        for (int l = 0; l < 4; l++) {
            int c = tid + l * 256;
            int row = c >> 5, cc = c & 31;
            const unsigned* src = Wu + (size_t)(k0 + row) * NC + bn + cc * 4;
            uint32_t dst = BsAddr + (uint32_t)(s * G_BS_STAGE + (row * 136 + cc * 4) * 4);
            cp16(dst, src, true);
        }
        cp_commit();
    };

    float acc[2][8][4];
#pragma unroll
    for (int mt = 0; mt < 2; mt++)
#pragma unroll
        for (int nt = 0; nt < 8; nt++)
#pragma unroll
            for (int i = 0; i < 4; i++) acc[mt][nt][i] = 0.f;

    const int T = K >> 5;
    issue_copy(0);
    if (T > 1) issue_copy(1);

    for (int t = 0; t < T; t++) {
        if (t + 2 < T)      { issue_copy(t + 2); cp_wait<2>(); }
        else if (t + 1 < T) { cp_wait<1>(); }
        else                { cp_wait<0>(); }
        __syncthreads();
        const int s = t % 3;
        const int k0 = t * 32;
#pragma unroll
        for (int q = 0; q < 4; q++) {
            const int kr = q * 8 + (lane & 3);
            float s0 = 1.f, h0 = 0.f, s4 = 1.f, h4 = 0.f;
            if (useBN) {
                s0 = scs[k0 + kr];     h0 = shs[k0 + kr];
                s4 = scs[k0 + kr + 4]; h4 = shs[k0 + kr + 4];
            }
            unsigned af[2][4], bf[8][2];
#pragma unroll
            for (int mt = 0; mt < 2; mt++) {
                int m = wm + mt * 16 + (lane >> 2);
                float a0 = cvtA(As[s][m][kr]),     a1 = cvtA(As[s][m + 8][kr]);
                float a2 = cvtA(As[s][m][kr + 4]), a3 = cvtA(As[s][m + 8][kr + 4]);
                if (useBN) {
                    a0 = fmaxf(fmaf(a0, s0, h0), 0.f);
                    a1 = fmaxf(fmaf(a1, s0, h0), 0.f);
                    a2 = fmaxf(fmaf(a2, s4, h4), 0.f);
                    a3 = fmaxf(fmaf(a3, s4, h4), 0.f);
                }
                af[mt][0] = f2tf32(a0); af[mt][1] = f2tf32(a1);
                af[mt][2] = f2tf32(a2); af[mt][3] = f2tf32(a3);
            }
#pragma unroll
            for (int nt = 0; nt < 8; nt++) {
                int n = wn + nt * 8 + (lane >> 2);
                bf[nt][0] = Bs[s][kr][n];
                bf[nt][1] = Bs[s][kr + 4][n];
            }
#pragma unroll
            for (int mt = 0; mt < 2; mt++)
#pragma unroll
                for (int nt = 0; nt < 8; nt++)
                    mma_tf32(acc[mt][nt], af[mt], bf[nt]);
        }
        __syncthreads();
    }

    // ---------------- epilogue: stage -> smem, warp-per-row coalesced ----------
#pragma unroll
    for (int mt = 0; mt < 2; mt++)
#pragma unroll
        for (int half = 0; half < 2; half++) {
            int r = wm + mt * 16 + (lane >> 2) + half * 8;
#pragma unroll
            for (int nt = 0; nt < 8; nt++) {
                int cl = wn + nt * 8 + 2 * (lane & 3);
                float2 v; v.x = acc[mt][nt][half * 2 + 0]; v.y = acc[mt][nt][half * 2 + 1];
                *(float2*)&Cs[r][cl] = v;
            }
        }
    if (sSum && tid < 128) { red0[tid] = 0.f; red1[tid] = 0.f; }
    __syncthreads();

    float4 bias = make_float4(0.f, 0.f, 0.f, 0.f);
    if (cBias) bias = *(const float4*)(cBias + bn + lane * 4);
    float psum[4] = {0.f, 0.f, 0.f, 0.f}, psq[4] = {0.f, 0.f, 0.f, 0.f};

#pragma unroll
    for (int i = 0; i < 16; i++) {
        int r = warp * 16 + i;
        int R = bm + r;
        if (R < M) {
            float4 v = *(const float4*)&Cs[r][lane * 4];
            v.x += bias.x; v.y += bias.y; v.z += bias.z; v.w += bias.w;
            if (outHalf) {
                __half* Ch = (__half*)Cout;
                *(uint2*)(Ch + (size_t)R * NC + bn + lane * 4) = pack_half4(v);
            } else {
                float* Cf = (float*)Cout;
                *(float4*)(Cf + (size_t)R * NC + bn + lane * 4) = v;
            }
            psum[0] += v.x; psum[1] += v.y; psum[2] += v.z; psum[3] += v.w;
            psq[0] += v.x * v.x; psq[1] += v.y * v.y;
            psq[2] += v.z * v.z; psq[3] += v.w * v.w;
        }
    }

    if (sSum) {
        __syncthreads();
#pragma unroll
        for (int j = 0; j < 4; j++) {
            atomicAdd(&red0[lane * 4 + j], psum[j]);
            atomicAdd(&red1[lane * 4 + j], psq[j]);
        }
        __syncthreads();
        if (tid < 128) {
            atomicAdd(&sSum[bn + tid], red0[tid]);
            atomicAdd(&sSq [bn + tid], red1[tid]);
        }
    }
}

// ---------------- pipelined edge message kernel (64-row tiles, full unroll) -----
// MSG[e] = edge_rep[e]@W3 + edge_attr[e]@We + be + P[src[e]] + Q[dst[e]], + stats
__global__ void __launch_bounds__(256, 3) edge_msg_kernel(
    const float* __restrict__ edge_rep, const float* __restrict__ edge_attr,
    const int* __restrict__ src, const int* __restrict__ dst,
    const float* __restrict__ be)
{
    float    (*As)[64][36]  = reinterpret_cast<float(*)[64][36]>(smem_raw);
    unsigned (*Bs)[32][136] = reinterpret_cast<unsigned(*)[32][136]>(smem_raw + E_AS_BYTES);
    float    (*Cs)[132]     = reinterpret_cast<float(*)[132]>(smem_raw);   // overlay
    float* red0 = (float*)(smem_raw + E_PIPE);
    float* red1 = red0 + 128;

    const int tid = threadIdx.x, lane = tid & 31, warp = tid >> 5;
    const int wm = (warp & 1) * 32, wn = (warp >> 1) * 32;
    const size_t bm = (size_t)blockIdx.x * 64;

    const uint32_t AsAddr = s2u(smem_raw);
    const uint32_t BsAddr = AsAddr + E_AS_BYTES;
    const unsigned* Wu = g_Wbuf + OFF_EDGE;

    // L2 prefetch of the P/Q gather rows (hidden behind mainloop)
    if (tid < 128) {
        int e0 = (int)bm + (tid >> 1);
        const __half* row = (tid & 1) ? (g_PQh + (size_t)dst[e0] * 256 + 128)
                                      : (g_PQh + (size_t)src[e0] * 256);
        asm volatile("prefetch.global.L2 [%0];" :: "l"(row));
        asm volatile("prefetch.global.L2 [%0];" :: "l"(row + 64));
    }

    auto issue_copy = [&](int t) {
        const int s = t & 1;
        if (t < 4) {
            const int k0 = t * 32;
#pragma unroll
            for (int l = 0; l < 2; l++) {
                int c = tid + l * 256;
                int row = c >> 3, cc = c & 7;
                const float* sp = edge_rep + (bm + row) * HDIM + k0 + cc * 4;
                uint32_t dp = AsAddr + (uint32_t)(s * E_AS_STAGE + (row * 36 + cc * 4) * 4);
                cp16(dp, sp, true);
            }
#pragma unroll
            for (int l = 0; l < 4; l++) {
                int c = tid + l * 256;
                int row = c >> 5, cc = c & 31;
                const unsigned* sp = Wu + (size_t)(k0 + row) * HDIM + cc * 4;
                uint32_t dp = BsAddr + (uint32_t)(s * E_BS_STAGE + (row * 136 + cc * 4) * 4);
                cp16(dp, sp, true);
            }
        } else {
            // edge encoder tail: K=16
            {
                int row = tid >> 2, cc = tid & 3;
                const float* sp = edge_attr + (bm + row) * EDIM + cc * 4;
                uint32_t dp = AsAddr + (uint32_t)(s * E_AS_STAGE + (row * 36 + cc * 4) * 4);
                cp16(dp, sp, true);
            }
#pragma unroll
            for (int l = 0; l < 2; l++) {
                int c = tid + l * 256;
                int row = c >> 5, cc = c & 31;
                const unsigned* sp = Wu + (size_t)(128 + row) * HDIM + cc * 4;
                uint32_t dp = BsAddr + (uint32_t)(s * E_BS_STAGE + (row * 136 + cc * 4) * 4);
                cp16(dp, sp, true);
            }
        }
        cp_commit();
    };

    float acc[2][4][4];
#pragma unroll
    for (int mt = 0; mt < 2; mt++)
#pragma unroll
        for (int nt = 0; nt < 4; nt++)
#pragma unroll
            for (int i = 0; i < 4; i++) acc[mt][nt][i] = 0.f;

    issue_copy(0);

#pragma unroll
    for (int t = 0; t < 5; t++) {
        cp_wait<0>();
        __syncthreads();
        if (t + 1 < 5) issue_copy(t + 1);
        const int s = t & 1;
        const int qmax = (t < 4) ? 4 : 2;
#pragma unroll
        for (int q = 0; q < 4; q++) {
            if (q >= qmax) break;
            const int kr = q * 8 + (lane & 3);
            unsigned af[2][4], bf[4][2];
#pragma unroll
            for (int mt = 0; mt < 2; mt++) {
                int m = wm + mt * 16 + (lane >> 2);
                af[mt][0] = f2tf32(As[s][m][kr]);
                af[mt][1] = f2tf32(As[s][m + 8][kr]);
                af[mt][2] = f2tf32(As[s][m][kr + 4]);
                af[mt][3] = f2tf32(As[s][m + 8][kr + 4]);
            }
#pragma unroll
            for (int nt = 0; nt < 4; nt++) {
                int n = wn + nt * 8 + (lane >> 2);
                bf[nt][0] = Bs[s][kr][n];
                bf[nt][1] = Bs[s][kr + 4][n];
            }
#pragma unroll
            for (int mt = 0; mt < 2; mt++)
#pragma unroll
                for (int nt = 0; nt < 4; nt++)
                    mma_tf32(acc[mt][nt], af[mt], bf[nt]);
        }
        __syncthreads();
    }

    // ---------------- epilogue: stage -> smem, warp-per-edge coalesced ---------
#pragma unroll
    for (int mt = 0; mt < 2; mt++)
#pragma unroll
        for (int half = 0; half < 2; half++) {
            int r = wm + mt * 16 + (lane >> 2) + half * 8;
#pragma unroll
            for (int nt = 0; nt < 4; nt++) {
                int cl = wn + nt * 8 + 2 * (lane & 3);
                float2 v; v.x = acc[mt][nt][half * 2 + 0]; v.y = acc[mt][nt][half * 2 + 1];
                *(float2*)&Cs[r][cl] = v;
            }
        }
    if (tid < 128) { red0[tid] = 0.f; red1[tid] = 0.f; }
    __syncthreads();

    float4 bev = *(const float4*)(be + lane * 4);
    float psum[4] = {0.f, 0.f, 0.f, 0.f}, psq[4] = {0.f, 0.f, 0.f, 0.f};

#pragma unroll
    for (int i = 0; i < 8; i++) {
        int r = warp * 8 + i;
        size_t e = bm + r;
        int s = src[e], d = dst[e];
        float4 pv = unpack_half4(*(const uint2*)(g_PQh + (size_t)s * 256 + lane * 4));
        float4 qv = unpack_half4(*(const uint2*)(g_PQh + (size_t)d * 256 + 128 + lane * 4));
        float4 v = *(const float4*)&Cs[r][lane * 4];
        v.x += pv.x + qv.x + bev.x;
        v.y += pv.y + qv.y + bev.y;
        v.z += pv.z + qv.z + bev.z;
        v.w += pv.w + qv.w + bev.w;
        *(uint2*)(g_MSGh + e * HDIM + lane * 4) = pack_half4(v);
        psum[0] += v.x; psum[1] += v.y; psum[2] += v.z; psum[3] += v.w;
        psq[0] += v.x * v.x; psq[1] += v.y * v.y;
        psq[2] += v.z * v.z; psq[3] += v.w * v.w;
    }

    __syncthreads();
#pragma unroll
    for (int j = 0; j < 4; j++) {
        atomicAdd(&red0[lane * 4 + j], psum[j]);
        atomicAdd(&red1[lane * 4 + j], psq[j]);
    }
    __syncthreads();
    if (tid < 128) {
        atomicAdd(&g_sum[tid], red0[tid]);
        atomicAdd(&g_sq [tid], red1[tid]);
    }
}

// ---------------- BN+ReLU+scatter with vector red ------------------------------
__global__ void scatter_kernel(const int* __restrict__ dst) {
    unsigned t = blockIdx.x * blockDim.x + threadIdx.x;
    size_t e = (size_t)(t >> 5);
    int c4 = (t & 31) * 4;
    if (e < (size_t)N_EDGES) {
        int d = dst[e];
        float4 m = unpack_half4(*(const uint2*)(g_MSGh + e * HDIM + c4));
        float v0 = fmaxf(fmaf(m.x, g_scaleArr[c4 + 0], g_shiftArr[c4 + 0]), 0.f);
        float v1 = fmaxf(fmaf(m.y, g_scaleArr[c4 + 1], g_shiftArr[c4 + 1]), 0.f);
        float v2 = fmaxf(fmaf(m.z, g_scaleArr[c4 + 2], g_shiftArr[c4 + 2]), 0.f);
        float v3 = fmaxf(fmaf(m.w, g_scaleArr[c4 + 3], g_shiftArr[c4 + 3]), 0.f);
        float* p = g_Y + (size_t)d * HDIM + c4;
        asm volatile("red.global.add.v4.f32 [%0], {%1,%2,%3,%4};"
                     :: "l"(p), "f"(v0), "f"(v1), "f"(v2), "f"(v3) : "memory");
    }
}

// ---------------- launch ------------------------------------------------------
extern "C" void kernel_launch(void* const* d_in, const int* in_sizes, int n_in,
                              void* d_out, int out_size) {
    const float* node_rep  = (const float*)d_in[0];
    const float* edge_rep  = (const float*)d_in[1];
    const float* edge_attr = (const float*)d_in[2];
    const int*   eidx      = (const int*)d_in[3];
    const float* W1  = (const float*)d_in[4];
    const float* W2  = (const float*)d_in[5];
    const float* W3  = (const float*)d_in[6];
    const float* We  = (const float*)d_in[7];
    const float* be  = (const float*)d_in[8];
    const float* bng = (const float*)d_in[9];
    const float* bnb = (const float*)d_in[10];
    const float* Wm1 = (const float*)d_in[11];
    const float* g1  = (const float*)d_in[12];
    const float* b1  = (const float*)d_in[13];
    const float* Wm2 = (const float*)d_in[14];
    const float* g2  = (const float*)d_in[15];
    const float* b2  = (const float*)d_in[16];
    const float* Wm3 = (const float*)d_in[17];
    const float* bm3 = (const float*)d_in[18];
    float* out = (float*)d_out;

    const int* src = eidx;
    const int* dst = eidx + N_EDGES;

    float *Y, *SUM, *SQ, *SCALE, *SHIFT;
    __half *PQh, *H1h, *H2h;
    unsigned* WB;
    cudaGetSymbolAddress((void**)&PQh, g_PQh);
    cudaGetSymbolAddress((void**)&Y,   g_Y);
    cudaGetSymbolAddress((void**)&H1h, g_H1h);
    cudaGetSymbolAddress((void**)&H2h, g_H2h);
    cudaGetSymbolAddress((void**)&SUM,   g_sum);
    cudaGetSymbolAddress((void**)&SQ,    g_sq);
    cudaGetSymbolAddress((void**)&SCALE, g_scaleArr);
    cudaGetSymbolAddress((void**)&SHIFT, g_shiftArr);
    cudaGetSymbolAddress((void**)&WB, g_Wbuf);

    const int GEMM_SMEM_F = 3 * (128 * 36 * 4) + G_BS_BYTES + 3072;  // 110592
    const int GEMM_SMEM_H = 3 * (128 * 40 * 2) + G_BS_BYTES + 3072;  // 86016
    const int EDGE_SMEM   = E_PIPE + 1024;                           // 54272
    cudaFuncSetAttribute(gemm_mma_kernel<float>,  cudaFuncAttributeMaxDynamicSharedMemorySize, GEMM_SMEM_F);
    cudaFuncSetAttribute(gemm_mma_kernel<__half>, cudaFuncAttributeMaxDynamicSharedMemorySize, GEMM_SMEM_H);
    cudaFuncSetAttribute(edge_msg_kernel, cudaFuncAttributeMaxDynamicSharedMemorySize, EDGE_SMEM);

    const int MBLK = (N_NODES + 127) / 128;  // 782

    prep_kernel<<<(W_TOTAL + 255) / 256, 256>>>(W1, W2, W3, We, Wm1, Wm2, Wm3);
    zero_y_stats_kernel<<<4096, 256>>>();

    // fused node linears: PQ = node_rep @ [W1|W2] -> fp16
    gemm_mma_kernel<float><<<dim3(2, MBLK), 256, GEMM_SMEM_F>>>(
        node_rep, WB + OFF_NODE, PQh, N_NODES, HDIM, 256, 1,
        nullptr, nullptr, nullptr, nullptr, nullptr);

    // edge GEMM + encoder + gathers + BN stats
    edge_msg_kernel<<<N_EDGES / 64, 256, EDGE_SMEM>>>(edge_rep, edge_attr, src, dst, be);

    bn_finalize_kernel<<<1, 128>>>(bng, bnb, 0, 128, 1.f / (float)N_EDGES);

    // BN + ReLU + scatter-sum
    scatter_kernel<<<(N_EDGES * 32) / 256, 256>>>(dst);

    // MLP layer 1: H1(fp16) = Y @ Wm1
    gemm_mma_kernel<float><<<dim3(2, MBLK), 256, GEMM_SMEM_F>>>(
        Y, WB + OFF_M1, H1h, N_NODES, HDIM, H2DIM, 1,
        nullptr, nullptr, nullptr, SUM + 128, SQ + 128);
    bn_finalize_kernel<<<2, 128>>>(g1, b1, 128, 256, 1.f / (float)N_NODES);

    // MLP layer 2: H2(fp16) = relu(bn1(H1)) @ Wm2
    gemm_mma_kernel<__half><<<dim3(2, MBLK), 256, GEMM_SMEM_H>>>(
        H1h, WB + OFF_M2, H2h, N_NODES, H2DIM, H2DIM, 1,
        SCALE + 128, SHIFT + 128, nullptr, SUM + 384, SQ + 384);
    bn_finalize_kernel<<<2, 128>>>(g2, b2, 384, 256, 1.f / (float)N_NODES);

    // MLP layer 3: out(fp32) = relu(bn2(H2)) @ Wm3 + bm3
    gemm_mma_kernel<__half><<<dim3(1, MBLK), 256, GEMM_SMEM_H>>>(
        H2h, WB + OFF_M3, out, N_NODES, H2DIM, HDIM, 0,
        SCALE + 384, SHIFT + 384, bm3, nullptr, nullptr);
}